// round 6
// baseline (speedup 1.0000x reference)
#include <cuda_runtime.h>
#include <cuda_bf16.h>
#include <cstdint>
#include <math.h>

// Problem constants
#define BATCH 16
#define NATOM 20
#define NEDGE 380            // 20*19
#define TSEQ  63             // T-1
#define HD    256            // hidden
#define G     1024           // 4*HD
#define NROWS (BATCH*NATOM)  // 320 motion rows
#define EROWS (BATCH*NEDGE)  // 6080 edge rows
#define EPAD  6144           // 48*128
#define HMROWS (NROWS*TSEQ)  // 20160
#define HMPAD  20224         // 158*128
#define MT_E 48
#define MT_G 158

// smem tile layout: A[128][256] bf16 and B[128][256] bf16, padded row stride
#define LDK_PAD 528                       // 512 + 16 bytes
#define SM_A 0
#define SM_B (128*LDK_PAD)
#define SMEM_SZ (2*128*LDK_PAD)           // 135168 bytes

// ---------------- device scratch ----------------
__device__ __nv_bfloat16 g_hmbf[HMPAD*HD];     // motion hidden bf16 [row*63+t][256]
__device__ float g_Qs[HMPAD*G];                // hm@WsP + bias, permuted cols
__device__ float g_Qr[HMPAD*G];                // hm@WrP, permuted cols
__device__ __nv_bfloat16 g_hbf[2][EPAD*HD];    // edge hidden bf16 ping-pong
__device__ float g_cE[EPAD*HD];                // edge cell fp32
__device__ float g_hn[2][NROWS*HD];            // motion h/c ping-pong (fp32)
__device__ float g_cn[2][NROWS*HD];
__device__ float g_Wcomb[4*G];                 // Wm@Wmi
__device__ float g_bcomb[G];                   // bm@Wmi + bmi
__device__ float g_qbias[G];                   // (be@Wei + bei + beh), permuted cols
__device__ __nv_bfloat16 g_WehI[1024*256];     // Weh^T, permuted rows, k-contig
__device__ __nv_bfloat16 g_WspI[2*1024*256];   // (We@Wei)^T halves, permuted, k-contig
__device__ int   g_send[NEDGE], g_rec[NEDGE], g_einv[NATOM*NATOM];
__device__ int   g_sB[EROWS], g_rB[EROWS];     // float-index base into Qs/Qr per edge row
__device__ float g_A[EROWS];

__device__ __forceinline__ float sigf(float x) { return 1.0f / (1.0f + expf(-x)); }
__device__ __forceinline__ float tanha(float x) {
    float y; asm("tanh.approx.f32 %0, %1;" : "=f"(y) : "f"(x)); return y;
}
__device__ __forceinline__ float siga(float x) { return fmaf(0.5f, tanha(0.5f*x), 0.5f); }

__device__ __forceinline__ uint32_t smem_u32(const void* p) {
    uint32_t a;
    asm("{ .reg .u64 t; cvta.to.shared.u64 t, %1; cvt.u32.u64 %0, t; }" : "=r"(a) : "l"(p));
    return a;
}

__device__ __forceinline__ void ldmx4(uint32_t& r0, uint32_t& r1, uint32_t& r2, uint32_t& r3,
                                      uint32_t addr) {
    asm volatile("ldmatrix.sync.aligned.m8n8.x4.shared.b16 {%0,%1,%2,%3}, [%4];"
                 : "=r"(r0), "=r"(r1), "=r"(r2), "=r"(r3) : "r"(addr));
}
__device__ __forceinline__ void mma16816(float* d, uint32_t a0, uint32_t a1, uint32_t a2,
                                         uint32_t a3, uint32_t b0, uint32_t b1) {
    asm volatile(
        "mma.sync.aligned.m16n8k16.row.col.f32.bf16.bf16.f32 "
        "{%0,%1,%2,%3},{%4,%5,%6,%7},{%8,%9},{%0,%1,%2,%3};"
        : "+f"(d[0]), "+f"(d[1]), "+f"(d[2]), "+f"(d[3])
        : "r"(a0), "r"(a1), "r"(a2), "r"(a3), "r"(b0), "r"(b1));
}

// Shared GEMM core: CTA computes acc[16 n8-tiles][4] = A(128x256) @ B^T(128x256),
// warp wid owns rows wid*16..wid*16+15, all 128 n-cols of the chunk.
__device__ __forceinline__ void gemm_core(char* smem, int tid, float acc[16][4]) {
    int lane = tid & 31, wid = tid >> 5;
#pragma unroll
    for (int i = 0; i < 16; i++)
#pragma unroll
        for (int q = 0; q < 4; q++) acc[i][q] = 0.f;
    uint32_t sbase = smem_u32(smem);
    uint32_t aadr = sbase + SM_A + (wid*16 + (lane & 15))*LDK_PAD + (lane >> 4)*16;
    uint32_t badr = sbase + SM_B + (lane & 15)*LDK_PAD + (lane >> 4)*16;
#pragma unroll 4
    for (int ks = 0; ks < 16; ks++) {
        uint32_t a0, a1, a2, a3;
        ldmx4(a0, a1, a2, a3, aadr + ks*32);
#pragma unroll
        for (int tp = 0; tp < 8; tp++) {
            uint32_t b0, b1, b2, b3;
            ldmx4(b0, b1, b2, b3, badr + tp*16*LDK_PAD + ks*32);
            mma16816(acc[2*tp],     a0, a1, a2, a3, b0, b2);
            mma16816(acc[2*tp + 1], a0, a1, a2, a3, b1, b3);
        }
    }
}

__device__ __forceinline__ void copy_tiles(char* smem, int tid,
                                           const uint4* __restrict__ As,
                                           const uint4* __restrict__ Bs) {
#pragma unroll
    for (int i = 0; i < 16; i++) {
        int idx = tid + i*256;
        int row = idx >> 5, c16 = idx & 31;
        *(uint4*)(smem + SM_A + row*LDK_PAD + c16*16) = As[idx];
        *(uint4*)(smem + SM_B + row*LDK_PAD + c16*16) = Bs[idx];
    }
    __syncthreads();
}

// ---------------- prep kernels ----------------
__global__ void prep_edges_k(const float* __restrict__ rel_rec,
                             const float* __restrict__ rel_send) {
    int e = blockIdx.x * blockDim.x + threadIdx.x;
    if (e >= NEDGE) return;
    int s = 0, r = 0;
    for (int n = 0; n < NATOM; n++) {
        if (rel_send[e*NATOM + n] > 0.5f) s = n;
        if (rel_rec [e*NATOM + n] > 0.5f) r = n;
    }
    g_send[e] = s; g_rec[e] = r;
    g_einv[s*NATOM + r] = e;
}

__global__ void prep_rowbase_k() {
    int grow = blockIdx.x * blockDim.x + threadIdx.x;
    if (grow >= EROWS) return;
    int b = grow / NEDGE, e = grow - b*NEDGE;
    g_sB[grow] = ((b*NATOM + g_send[e])*TSEQ)*G;
    g_rB[grow] = ((b*NATOM + g_rec [e])*TSEQ)*G;
}

__global__ void prep_small_k(const float* __restrict__ Wm, const float* __restrict__ bm,
                             const float* __restrict__ Wmi, const float* __restrict__ bmi,
                             const float* __restrict__ be, const float* __restrict__ Wei,
                             const float* __restrict__ bei, const float* __restrict__ beh) {
    int g = blockIdx.x * blockDim.x + threadIdx.x;
    if (g >= G) return;
    for (int d = 0; d < 4; d++) {
        float s = 0.f;
        for (int k = 0; k < 128; k++) s += Wm[d*128 + k] * Wmi[k*G + g];
        g_Wcomb[d*G + g] = s;
    }
    float sb = 0.f, sc = 0.f;
    for (int k = 0; k < 128; k++) {
        sb += bm[k] * Wmi[k*G + g];
        sc += be[k] * Wei[k*G + g];
    }
    g_bcomb[g] = sb + bmi[g];
    // permuted column: n = chunk*128 + gate*32 + j_local, chunk = j>>5
    int gate = g >> 8, j = g & 255;
    int cc = j >> 5, jl = j & 31;
    g_qbias[cc*128 + gate*32 + jl] = sc + bei[g] + beh[g];
}

// Weh^T -> permuted row-major bf16 image [n][k], n = c*128 + gate*32 + jl
__global__ void prep_wehI_k(const float* __restrict__ Weh) {
    int id = blockIdx.x * blockDim.x + threadIdx.x;
    if (id >= 1024*256) return;
    int n = id >> 8, k = id & 255;
    int cc = n >> 7, rem = n & 127, gate = rem >> 5, jl = rem & 31;
    int j = cc*32 + jl;
    g_WehI[n*256 + k] = __float2bfloat16(Weh[k*G + gate*256 + j]);
}

// (We@Wei)^T halves -> permuted bf16 image
__global__ void prep_wspI_k(const float* __restrict__ We, const float* __restrict__ Wei) {
    int id = blockIdx.x * blockDim.x + threadIdx.x;
    if (id >= 2*256*1024) return;
    int which = id >> 18;
    int k = (id >> 10) & 255;
    int n = id & 1023;
    int cc = n >> 7, rem = n & 127, gate = rem >> 5, jl = rem & 31;
    int gcol = gate*256 + cc*32 + jl;
    const float* Wrow = We + (which*HD + k) * 128;
    float s = 0.f;
    for (int d = 0; d < 128; d++) s += Wrow[d] * Wei[d*G + gcol];
    g_WspI[(which*1024 + n)*256 + k] = __float2bfloat16(s);
}

__global__ void zero_state_k() {
    int i = blockIdx.x * blockDim.x + threadIdx.x;
    if (i < EPAD*HD) {
        g_hbf[0][i] = __float2bfloat16(0.f);
        g_hbf[1][i] = __float2bfloat16(0.f);
        g_cE[i] = 0.f;
    }
    if (i < NROWS*HD) { g_hn[0][i] = 0.f; g_cn[0][i] = 0.f; }
    if (i < (HMPAD - HMROWS)*HD) g_hmbf[HMROWS*HD + i] = __float2bfloat16(0.f);
}

// ---------------- motion LSTM step (fp32 SIMT, exact) ----------------
template<int RT>
__global__ void motion_step_k(const float* __restrict__ X,
                              const float* __restrict__ Wh,
                              const float* __restrict__ bh,
                              int t, int par) {
    __shared__ float Hs[RT][HD];
    const float* h_in = g_hn[par];
    const float* c_in = g_cn[par];
    float* h_out = g_hn[par ^ 1];
    float* c_out = g_cn[par ^ 1];
    int j  = blockIdx.x * 128 + threadIdx.x;
    int r0 = blockIdx.y * RT;
    for (int idx = threadIdx.x; idx < RT*HD; idx += 128)
        Hs[idx / HD][idx % HD] = h_in[(r0 + idx / HD)*HD + (idx % HD)];
    __syncthreads();

    float a0[RT], a1[RT], a2[RT], a3[RT];
#pragma unroll
    for (int r = 0; r < RT; r++) { a0[r]=0.f; a1[r]=0.f; a2[r]=0.f; a3[r]=0.f; }
#pragma unroll 4
    for (int k = 0; k < HD; k++) {
        float w0 = Wh[k*G + j];
        float w1 = Wh[k*G + 256 + j];
        float w2 = Wh[k*G + 512 + j];
        float w3 = Wh[k*G + 768 + j];
#pragma unroll
        for (int r = 0; r < RT; r++) {
            float hv = Hs[r][k];
            a0[r] += w0*hv; a1[r] += w1*hv; a2[r] += w2*hv; a3[r] += w3*hv;
        }
    }
#pragma unroll
    for (int r = 0; r < RT; r++) {
        int row = r0 + r;
        const float* xp = X + row*64*4 + t*4;
        float d0 = xp[4]-xp[0], d1 = xp[5]-xp[1], d2 = xp[6]-xp[2], d3 = xp[7]-xp[3];
        float pre[4];
#pragma unroll
        for (int gq = 0; gq < 4; gq++) {
            int gc = gq*256 + j;
            pre[gq] = g_bcomb[gc] + bh[gc]
                    + d0*g_Wcomb[0*G+gc] + d1*g_Wcomb[1*G+gc]
                    + d2*g_Wcomb[2*G+gc] + d3*g_Wcomb[3*G+gc];
        }
        float iv = sigf(pre[0] + a0[r]);
        float fv = sigf(pre[1] + a1[r]);
        float gv = tanhf(pre[2] + a2[r]);
        float ov = sigf(pre[3] + a3[r]);
        float cv = fv * c_in[row*HD + j] + iv * gv;
        float hv = ov * tanhf(cv);
        c_out[row*HD + j] = cv;
        h_out[row*HD + j] = hv;
        g_hmbf[(row*TSEQ + t)*HD + j] = __float2bfloat16(hv);
    }
}

// ---------------- TC GEMM: Q{s,r} = hmbf @ WspI (+bias for mode 0) ----------------
__global__ void __launch_bounds__(256) gemm_tc_k(int mode) {
    extern __shared__ char smem[];
    int tid = threadIdx.x;
    int c = blockIdx.x, m = blockIdx.y;
    const uint4* As = (const uint4*)(g_hmbf + (size_t)m*128*HD);
    const uint4* Bs = (const uint4*)g_WspI + (size_t)mode*32768 + (size_t)c*4096;
    copy_tiles(smem, tid, As, Bs);

    float acc[16][4];
    gemm_core(smem, tid, acc);

    int lane = tid & 31, wid = tid >> 5;
    int row0 = m*128 + wid*16 + (lane >> 2);
    float* Qout = mode ? g_Qr : g_Qs;
#pragma unroll
    for (int rr = 0; rr < 2; rr++) {
        int grow = row0 + rr*8;
        if (grow >= HMROWS) continue;
        float* out = Qout + (size_t)grow*G + c*128;
#pragma unroll
        for (int tile = 0; tile < 16; tile++) {
            int c0 = tile*8 + 2*(lane & 3);
            float v0 = acc[tile][rr*2 + 0];
            float v1 = acc[tile][rr*2 + 1];
            if (mode == 0) {
                v0 += g_qbias[c*128 + c0];
                v1 += g_qbias[c*128 + c0 + 1];
            }
            *(float2*)(out + c0) = make_float2(v0, v1);
        }
    }
}

// ---------------- TC edge LSTM step ----------------
__global__ void __launch_bounds__(256) edge_tc_k(int t, int par) {
    extern __shared__ char smem[];
    int tid = threadIdx.x;
    int c = blockIdx.x, m = blockIdx.y;
    const uint4* As = (const uint4*)(g_hbf[par] + (size_t)m*128*HD);
    const uint4* Bs = (const uint4*)g_WehI + (size_t)c*4096;
    copy_tiles(smem, tid, As, Bs);

    float acc[16][4];
    gemm_core(smem, tid, acc);

    int lane = tid & 31, wid = tid >> 5;
    int row0 = m*128 + wid*16 + (lane >> 2);
    __nv_bfloat16* hOut = g_hbf[par ^ 1];
#pragma unroll
    for (int rr = 0; rr < 2; rr++) {
        int grow = row0 + rr*8;
        if (grow >= EROWS) continue;
        int qoff = t*G + c*128;
        const float* QsP = g_Qs + g_sB[grow] + qoff;
        const float* QrP = g_Qr + g_rB[grow] + qoff;
        float* cP = g_cE + (size_t)grow*HD + c*32;
        __nv_bfloat16* hP = hOut + (size_t)grow*HD + c*32;
#pragma unroll
        for (int tq = 0; tq < 4; tq++) {
#pragma unroll
            for (int d = 0; d < 2; d++) {
                int jl = tq*8 + 2*(lane & 3) + d;
                float pi = acc[0*4 + tq][rr*2 + d] + QsP[0*32 + jl] + QrP[0*32 + jl];
                float pf = acc[1*4 + tq][rr*2 + d] + QsP[1*32 + jl] + QrP[1*32 + jl];
                float pg = acc[2*4 + tq][rr*2 + d] + QsP[2*32 + jl] + QrP[2*32 + jl];
                float po = acc[3*4 + tq][rr*2 + d] + QsP[3*32 + jl] + QrP[3*32 + jl];
                float iv = siga(pi), fv = siga(pf), gv = tanha(pg), ov = siga(po);
                float cn = fmaf(fv, cP[jl], iv*gv);
                cP[jl] = cn;
                hP[jl] = __float2bfloat16(ov * tanha(cn));
            }
        }
    }
}

// ---------------- finalization ----------------
__global__ void score_k(const float* __restrict__ Wf, const float* __restrict__ bf) {
    int row = blockIdx.x * blockDim.x + threadIdx.x;
    if (row >= EROWS) return;
    const __nv_bfloat16* h = g_hbf[1] + (size_t)row*HD;
    float s = 0.f;
    for (int k = 0; k < HD; k++) s += __bfloat162float(h[k]) * Wf[k];
    g_A[row] = sigf(s + bf[0]);
}

__global__ void assemble_k(float* __restrict__ out) {
    int i = blockIdx.x * blockDim.x + threadIdx.x;
    if (i >= BATCH*NATOM*NATOM) return;
    int b = i / (NATOM*NATOM);
    int nm = i % (NATOM*NATOM);
    int n = nm / NATOM, mm = nm % NATOM;
    float v = 0.f;
    if (n != mm) {
        int e1 = g_einv[n*NATOM + mm];
        int e2 = g_einv[mm*NATOM + n];
        v = 0.5f * (g_A[b*NEDGE + e1] + g_A[b*NEDGE + e2]);
    }
    out[i] = v;
}

// ---------------- launcher ----------------
extern "C" void kernel_launch(void* const* d_in, const int* in_sizes, int n_in,
                              void* d_out, int out_size) {
    const float* X        = (const float*)d_in[0];
    const float* rel_rec  = (const float*)d_in[1];
    const float* rel_send = (const float*)d_in[2];
    const float* Wm  = (const float*)d_in[3];
    const float* bm  = (const float*)d_in[4];
    const float* Wmi = (const float*)d_in[5];
    const float* bmi = (const float*)d_in[6];
    const float* Wmh = (const float*)d_in[7];
    const float* bmh = (const float*)d_in[8];
    const float* We  = (const float*)d_in[9];
    const float* be  = (const float*)d_in[10];
    const float* Wei = (const float*)d_in[11];
    const float* bei = (const float*)d_in[12];
    const float* Weh = (const float*)d_in[13];
    const float* beh = (const float*)d_in[14];
    const float* Wf  = (const float*)d_in[15];
    const float* bf  = (const float*)d_in[16];
    float* out = (float*)d_out;

    static bool attr_done = false;
    if (!attr_done) {
        (void)cudaFuncSetAttribute(gemm_tc_k, cudaFuncAttributeMaxDynamicSharedMemorySize, SMEM_SZ);
        (void)cudaFuncSetAttribute(edge_tc_k, cudaFuncAttributeMaxDynamicSharedMemorySize, SMEM_SZ);
        attr_done = true;
    }

    prep_edges_k<<<2, 256>>>(rel_rec, rel_send);
    prep_rowbase_k<<<(EROWS + 255)/256, 256>>>();
    prep_small_k<<<4, 256>>>(Wm, bm, Wmi, bmi, be, Wei, bei, beh);
    prep_wehI_k<<<(1024*256 + 255)/256, 256>>>(Weh);
    prep_wspI_k<<<(2*256*1024 + 255)/256, 256>>>(We, Wei);
    zero_state_k<<<(EPAD*HD + 255)/256, 256>>>();

    for (int t = 0; t < TSEQ; t++)
        motion_step_k<4><<<dim3(2, NROWS/4), 128>>>(X, Wmh, bmh, t, t & 1);

    gemm_tc_k<<<dim3(8, MT_G), 256, SMEM_SZ>>>(0);
    gemm_tc_k<<<dim3(8, MT_G), 256, SMEM_SZ>>>(1);

    for (int t = 0; t < TSEQ; t++)
        edge_tc_k<<<dim3(8, MT_E), 256, SMEM_SZ>>>(t, t & 1);

    score_k<<<(EROWS + 255)/256, 256>>>(Wf, bf);
    assemble_k<<<(BATCH*NATOM*NATOM + 255)/256, 256>>>(out);
}

// round 12
// speedup vs baseline: 1.2295x; 1.2295x over previous
#include <cuda_runtime.h>
#include <cuda_bf16.h>
#include <cstdint>
#include <math.h>

#define BATCH 16
#define NATOM 20
#define NEDGE 380
#define TSEQ  63
#define HD    256
#define G     1024
#define NROWS 320
#define EROWS 6080
#define EPAD  6144
#define HMROWS 20160
#define HMPAD  20224
#define MT_G 158
#define NCTA 128

#define LDK 528
#define ABYTES (128*LDK)            // 67584
#define BOFF   (2*ABYTES)
#define SMEM_E (3*ABYTES)           // 202752 (persistent edge kernel)
#define SMEM_Q (2*ABYTES)           // 135168 (Q GEMM kernel)

// ---------------- device scratch ----------------
__device__ __nv_bfloat16 g_hmbf[HMPAD*HD];
__device__ __nv_bfloat16 g_Qs[HMPAD*G];        // bf16, permuted cols, +bias
__device__ __nv_bfloat16 g_Qr[HMPAD*G];
__device__ __nv_bfloat16 g_hbf[2][EPAD*HD];
__device__ float g_hn[2][NROWS*HD];
__device__ float g_cn[2][NROWS*HD];
__device__ float g_Wcomb[4*G];
__device__ float g_bcomb[G];
__device__ float g_qbias[G];                   // permuted
__device__ __nv_bfloat16 g_WehI[G*HD];
__device__ __nv_bfloat16 g_WspI[2*G*HD];
__device__ int g_send[NEDGE], g_rec[NEDGE], g_einv[NATOM*NATOM];
__device__ int g_sB[EPAD], g_rB[EPAD];
__device__ float g_A[EROWS];
__device__ unsigned g_barCnt;
__device__ volatile unsigned g_barGen;

__device__ __forceinline__ float sigf(float x) { return 1.0f / (1.0f + expf(-x)); }
__device__ __forceinline__ float tanha(float x) {
    float y; asm("tanh.approx.f32 %0, %1;" : "=f"(y) : "f"(x)); return y;
}
__device__ __forceinline__ float siga(float x) { return fmaf(0.5f, tanha(0.5f*x), 0.5f); }
__device__ __forceinline__ uint32_t smem_u32(const void* p) {
    uint32_t a;
    asm("{ .reg .u64 t; cvta.to.shared.u64 t, %1; cvt.u32.u64 %0, t; }" : "=r"(a) : "l"(p));
    return a;
}
__device__ __forceinline__ void ldmx4(uint32_t& r0, uint32_t& r1, uint32_t& r2, uint32_t& r3,
                                      uint32_t addr) {
    asm volatile("ldmatrix.sync.aligned.m8n8.x4.shared.b16 {%0,%1,%2,%3}, [%4];"
                 : "=r"(r0), "=r"(r1), "=r"(r2), "=r"(r3) : "r"(addr));
}
__device__ __forceinline__ void mma16816(float* d, uint32_t a0, uint32_t a1, uint32_t a2,
                                         uint32_t a3, uint32_t b0, uint32_t b1) {
    asm volatile(
        "mma.sync.aligned.m16n8k16.row.col.f32.bf16.bf16.f32 "
        "{%0,%1,%2,%3},{%4,%5,%6,%7},{%8,%9},{%0,%1,%2,%3};"
        : "+f"(d[0]), "+f"(d[1]), "+f"(d[2]), "+f"(d[3])
        : "r"(a0), "r"(a1), "r"(a2), "r"(a3), "r"(b0), "r"(b1));
}
__device__ __forceinline__ float2 ldbf2(const __nv_bfloat16* p) {
    return __bfloat1622float2(*(const __nv_bfloat162*)p);
}
__device__ __forceinline__ void stbf2(__nv_bfloat16* p, float a, float b) {
    *(__nv_bfloat162*)p = __floats2bfloat162_rn(a, b);
}
__device__ __forceinline__ void cpasync16(uint32_t dst, const void* src) {
    asm volatile("cp.async.cg.shared.global [%0], [%1], 16;" :: "r"(dst), "l"(src));
}
#define CP_COMMIT() asm volatile("cp.async.commit_group;" ::: "memory")
#define CP_WAIT1()  asm volatile("cp.async.wait_group 1;" ::: "memory")
#define CP_WAIT0()  asm volatile("cp.async.wait_group 0;" ::: "memory")

// bounded-spin grid barrier: if co-residency ever breaks we produce wrong
// results (diagnostic) instead of hanging the container.
__device__ __forceinline__ void gbar() {
    __threadfence();
    __syncthreads();
    if (threadIdx.x == 0) {
        unsigned g = g_barGen;
        if (atomicAdd(&g_barCnt, 1) == NCTA - 1) {
            g_barCnt = 0;
            __threadfence();
            g_barGen = g + 1;
        } else {
            int it = 0;
            while (g_barGen == g && it < (1 << 21)) { __nanosleep(64); it++; }
            __threadfence();
        }
    }
    __syncthreads();
}

// acc[16][4] = A(128x256,@abuf) @ B(128x256,@BOFF)^T
__device__ __forceinline__ void gemm128(uint32_t sbase, uint32_t abuf, int lane, int wid,
                                        float acc[16][4]) {
#pragma unroll
    for (int i = 0; i < 16; i++)
#pragma unroll
        for (int q = 0; q < 4; q++) acc[i][q] = 0.f;
    uint32_t aadr = sbase + abuf + (wid*16 + (lane & 15))*LDK + (lane >> 4)*16;
    uint32_t badr = sbase + BOFF + (lane & 15)*LDK + (lane >> 4)*16;
#pragma unroll 4
    for (int ks = 0; ks < 16; ks++) {
        uint32_t a0, a1, a2, a3;
        ldmx4(a0, a1, a2, a3, aadr + ks*32);
#pragma unroll
        for (int tp = 0; tp < 8; tp++) {
            uint32_t b0, b1, b2, b3;
            ldmx4(b0, b1, b2, b3, badr + tp*16*LDK + ks*32);
            mma16816(acc[2*tp],     a0, a1, a2, a3, b0, b2);
            mma16816(acc[2*tp + 1], a0, a1, a2, a3, b1, b3);
        }
    }
}
__device__ __forceinline__ void copyA_async(uint32_t sdst, const __nv_bfloat16* src, int tid) {
    const char* s = (const char*)src;
#pragma unroll
    for (int i = 0; i < 16; i++) {
        int idx = tid + i*256;
        cpasync16(sdst + (idx >> 5)*LDK + (idx & 31)*16, s + idx*16);
    }
}
__device__ __forceinline__ void copyB(char* smem, int tid, const __nv_bfloat16* src) {
    const uint4* s = (const uint4*)src;
#pragma unroll
    for (int i = 0; i < 16; i++) {
        int idx = tid + i*256;
        *(uint4*)(smem + BOFF + (idx >> 5)*LDK + (idx & 31)*16) = s[idx];
    }
}

// ---------------- prep kernels ----------------
__global__ void prep_edges_k(const float* __restrict__ rel_rec,
                             const float* __restrict__ rel_send) {
    int e = blockIdx.x * blockDim.x + threadIdx.x;
    if (e >= NEDGE) return;
    int s = 0, r = 0;
    for (int n = 0; n < NATOM; n++) {
        if (rel_send[e*NATOM + n] > 0.5f) s = n;
        if (rel_rec [e*NATOM + n] > 0.5f) r = n;
    }
    g_send[e] = s; g_rec[e] = r;
    g_einv[s*NATOM + r] = e;
}
__global__ void prep_rowbase_k() {
    int grow = blockIdx.x * blockDim.x + threadIdx.x;
    if (grow >= EPAD) return;
    if (grow < EROWS) {
        int b = grow / NEDGE, e = grow - b*NEDGE;
        g_sB[grow] = ((b*NATOM + g_send[e])*TSEQ)*G;
        g_rB[grow] = ((b*NATOM + g_rec [e])*TSEQ)*G;
    } else { g_sB[grow] = 0; g_rB[grow] = 0; }
}
__global__ void prep_small_k(const float* __restrict__ Wm, const float* __restrict__ bm,
                             const float* __restrict__ Wmi, const float* __restrict__ bmi,
                             const float* __restrict__ be, const float* __restrict__ Wei,
                             const float* __restrict__ bei, const float* __restrict__ beh) {
    int g = blockIdx.x * blockDim.x + threadIdx.x;
    if (g >= G) return;
    for (int d = 0; d < 4; d++) {
        float s = 0.f;
        for (int k = 0; k < 128; k++) s += Wm[d*128 + k] * Wmi[k*G + g];
        g_Wcomb[d*G + g] = s;
    }
    float sb = 0.f, sc = 0.f;
    for (int k = 0; k < 128; k++) {
        sb += bm[k] * Wmi[k*G + g];
        sc += be[k] * Wei[k*G + g];
    }
    g_bcomb[g] = sb + bmi[g];
    int gate = g >> 8, j = g & 255;
    g_qbias[(j >> 5)*128 + gate*32 + (j & 31)] = sc + bei[g] + beh[g];
}
__global__ void prep_wehI_k(const float* __restrict__ Weh) {
    int id = blockIdx.x * blockDim.x + threadIdx.x;
    if (id >= G*HD) return;
    int n = id >> 8, k = id & 255;
    int cc = n >> 7, rem = n & 127, gate = rem >> 5, jl = rem & 31;
    g_WehI[n*HD + k] = __float2bfloat16(Weh[k*G + gate*256 + cc*32 + jl]);
}
__global__ void prep_wspI_k(const float* __restrict__ We, const float* __restrict__ Wei) {
    int id = blockIdx.x * blockDim.x + threadIdx.x;
    if (id >= 2*G*HD) return;
    int which = id >> 18;
    int k = (id >> 10) & 255;
    int n = id & 1023;
    int cc = n >> 7, rem = n & 127, gate = rem >> 5, jl = rem & 31;
    int gcol = gate*256 + cc*32 + jl;
    const float4* W4 = (const float4*)(We + (which*HD + k)*128);
    float s = 0.f;
#pragma unroll 8
    for (int d4 = 0; d4 < 32; d4++) {
        float4 w = W4[d4];
        s += w.x*Wei[(4*d4+0)*G+gcol] + w.y*Wei[(4*d4+1)*G+gcol]
           + w.z*Wei[(4*d4+2)*G+gcol] + w.w*Wei[(4*d4+3)*G+gcol];
    }
    g_WspI[(which*G + n)*HD + k] = __float2bfloat16(s);
}
__global__ void zero_state_k() {
    int i = blockIdx.x * blockDim.x + threadIdx.x;
    if (i < EPAD*HD) {
        g_hbf[0][i] = __float2bfloat16(0.f);
        g_hbf[1][i] = __float2bfloat16(0.f);
    }
    if (i < NROWS*HD) { g_hn[0][i] = 0.f; g_cn[0][i] = 0.f; }
    if (i < (HMPAD - HMROWS)*HD) g_hmbf[HMROWS*HD + i] = __float2bfloat16(0.f);
}

// ---------------- motion LSTM step (fp32 SIMT, exact) ----------------
template<int RT>
__global__ void motion_step_k(const float* __restrict__ X,
                              const float* __restrict__ Wh,
                              const float* __restrict__ bh,
                              int t, int par) {
    __shared__ float Hs[RT][HD];
    const float* h_in = g_hn[par];
    const float* c_in = g_cn[par];
    float* h_out = g_hn[par ^ 1];
    float* c_out = g_cn[par ^ 1];
    int j  = blockIdx.x * 128 + threadIdx.x;
    int r0 = blockIdx.y * RT;
    for (int idx = threadIdx.x; idx < RT*HD; idx += 128)
        Hs[idx / HD][idx % HD] = h_in[(r0 + idx / HD)*HD + (idx % HD)];
    __syncthreads();

    float a0[RT], a1[RT], a2[RT], a3[RT];
#pragma unroll
    for (int r = 0; r < RT; r++) { a0[r]=0.f; a1[r]=0.f; a2[r]=0.f; a3[r]=0.f; }
#pragma unroll 4
    for (int k = 0; k < HD; k++) {
        float w0 = Wh[k*G + j];
        float w1 = Wh[k*G + 256 + j];
        float w2 = Wh[k*G + 512 + j];
        float w3 = Wh[k*G + 768 + j];
#pragma unroll
        for (int r = 0; r < RT; r++) {
            float hv = Hs[r][k];
            a0[r] += w0*hv; a1[r] += w1*hv; a2[r] += w2*hv; a3[r] += w3*hv;
        }
    }
#pragma unroll
    for (int r = 0; r < RT; r++) {
        int row = r0 + r;
        const float* xp = X + row*64*4 + t*4;
        float d0 = xp[4]-xp[0], d1 = xp[5]-xp[1], d2 = xp[6]-xp[2], d3 = xp[7]-xp[3];
        float pre[4];
#pragma unroll
        for (int gq = 0; gq < 4; gq++) {
            int gc = gq*256 + j;
            pre[gq] = g_bcomb[gc] + bh[gc]
                    + d0*g_Wcomb[0*G+gc] + d1*g_Wcomb[1*G+gc]
                    + d2*g_Wcomb[2*G+gc] + d3*g_Wcomb[3*G+gc];
        }
        float iv = sigf(pre[0] + a0[r]);
        float fv = sigf(pre[1] + a1[r]);
        float gv = tanhf(pre[2] + a2[r]);
        float ov = sigf(pre[3] + a3[r]);
        float cv = fv * c_in[row*HD + j] + iv * gv;
        float hv = ov * tanhf(cv);
        c_out[row*HD + j] = cv;
        h_out[row*HD + j] = hv;
        g_hmbf[(row*TSEQ + t)*HD + j] = __float2bfloat16(hv);
    }
}

// ---------------- TC GEMM: Q{s,r} = hmbf @ WspI (+bias mode 0), bf16 out ----------------
__global__ void __launch_bounds__(256) gemm_tc_k(int mode) {
    extern __shared__ char smem[];
    int tid = threadIdx.x;
    int c = blockIdx.x, m = blockIdx.y;
    uint32_t sbase = smem_u32(smem);
    // A at buf0, B at BOFF... but SMEM_Q only has 2 buffers: put B at ABYTES.
    {
        const uint4* As = (const uint4*)(g_hmbf + (size_t)m*128*HD);
        const uint4* Bs = (const uint4*)(g_WspI + (size_t)(mode*G + c*128)*HD);
#pragma unroll
        for (int i = 0; i < 16; i++) {
            int idx = tid + i*256;
            *(uint4*)(smem + (idx >> 5)*LDK + (idx & 31)*16) = As[idx];
            *(uint4*)(smem + ABYTES + (idx >> 5)*LDK + (idx & 31)*16) = Bs[idx];
        }
        __syncthreads();
    }
    int lane = tid & 31, wid = tid >> 5;
    float acc[16][4];
    // inline gemm with B at ABYTES
#pragma unroll
    for (int i = 0; i < 16; i++)
#pragma unroll
        for (int q = 0; q < 4; q++) acc[i][q] = 0.f;
    {
        uint32_t aadr = sbase + (wid*16 + (lane & 15))*LDK + (lane >> 4)*16;
        uint32_t badr = sbase + ABYTES + (lane & 15)*LDK + (lane >> 4)*16;
#pragma unroll 4
        for (int ks = 0; ks < 16; ks++) {
            uint32_t a0, a1, a2, a3;
            ldmx4(a0, a1, a2, a3, aadr + ks*32);
#pragma unroll
            for (int tp = 0; tp < 8; tp++) {
                uint32_t b0, b1, b2, b3;
                ldmx4(b0, b1, b2, b3, badr + tp*16*LDK + ks*32);
                mma16816(acc[2*tp],     a0, a1, a2, a3, b0, b2);
                mma16816(acc[2*tp + 1], a0, a1, a2, a3, b1, b3);
            }
        }
    }
    int row0 = m*128 + wid*16 + (lane >> 2);
    __nv_bfloat16* Qout = mode ? g_Qr : g_Qs;
#pragma unroll
    for (int rr = 0; rr < 2; rr++) {
        int grow = row0 + rr*8;
        if (grow >= HMROWS) continue;
        __nv_bfloat16* op = Qout + (size_t)grow*G + c*128 + 2*(lane & 3);
#pragma unroll
        for (int tt = 0; tt < 16; tt++) {
            float v0 = acc[tt][rr*2], v1 = acc[tt][rr*2+1];
            if (mode == 0) {
                int c0 = c*128 + tt*8 + 2*(lane & 3);
                v0 += g_qbias[c0]; v1 += g_qbias[c0 + 1];
            }
            stbf2(op + tt*8, v0, v1);
        }
    }
}

// ---------------- persistent edge LSTM (the only persistent piece) ----------------
__global__ void __launch_bounds__(256, 1) edge_pers_k() {
    extern __shared__ char smem[];
    int tid = threadIdx.x, c = blockIdx.x;
    int lane = tid & 31, wid = tid >> 5;
    uint32_t sbase = smem_u32(smem);
    int chunk = c & 7, mg = c >> 3;         // 8 chunks x 16 groups, 3 m-tiles/group

    copyB(smem, tid, g_WehI + (size_t)chunk*128*HD);   // Weh chunk resident all 63 steps
    float cR[3][16];
#pragma unroll
    for (int j = 0; j < 3; j++)
#pragma unroll
        for (int i = 0; i < 16; i++) cR[j][i] = 0.f;

    for (int t = 0; t < TSEQ; t++) {
        int par = t & 1;
        const __nv_bfloat16* hIn = g_hbf[par];
        __nv_bfloat16* hOut = g_hbf[par ^ 1];
        copyA_async(sbase, hIn + (size_t)(mg*3)*128*HD, tid);
        CP_COMMIT();
#pragma unroll 1
        for (int jj = 0; jj < 3; jj++) {
            if (jj < 2) {
                copyA_async(sbase + ((jj+1) & 1)*ABYTES,
                            hIn + (size_t)(mg*3 + jj + 1)*128*HD, tid);
                CP_COMMIT(); CP_WAIT1();
            } else {
                CP_WAIT0();
            }
            __syncthreads();
            float acc[16][4];
            gemm128(sbase, (jj & 1)*ABYTES, lane, wid, acc);
            __syncthreads();
            int row0 = (mg*3 + jj)*128 + wid*16 + (lane >> 2);
#pragma unroll
            for (int rr = 0; rr < 2; rr++) {
                int grow = row0 + rr*8;
                const __nv_bfloat16* qs = g_Qs + g_sB[grow] + t*G + chunk*128;
                const __nv_bfloat16* qr = g_Qr + g_rB[grow] + t*G + chunk*128;
                __nv_bfloat16* hp = hOut + (size_t)grow*HD + chunk*32;
#pragma unroll
                for (int tq = 0; tq < 4; tq++) {
                    int off = tq*8 + 2*(lane & 3);
                    float2 si = ldbf2(qs + off),      ri = ldbf2(qr + off);
                    float2 sf = ldbf2(qs + 32 + off), rf = ldbf2(qr + 32 + off);
                    float2 sg = ldbf2(qs + 64 + off), rg = ldbf2(qr + 64 + off);
                    float2 so = ldbf2(qs + 96 + off), ro = ldbf2(qr + 96 + off);
                    float hv[2];
#pragma unroll
                    for (int d = 0; d < 2; d++) {
                        float pi = acc[0*4+tq][rr*2+d] + (d ? si.y + ri.y : si.x + ri.x);
                        float pf = acc[1*4+tq][rr*2+d] + (d ? sf.y + rf.y : sf.x + rf.x);
                        float pg = acc[2*4+tq][rr*2+d] + (d ? sg.y + rg.y : sg.x + rg.x);
                        float po = acc[3*4+tq][rr*2+d] + (d ? so.y + ro.y : so.x + ro.x);
                        int ci = rr*8 + tq*2 + d;
                        float iv = siga(pi), fv = siga(pf), gv = tanha(pg), ov = siga(po);
                        float cn = fmaf(fv, cR[jj][ci], iv*gv);
                        cR[jj][ci] = cn;
                        hv[d] = ov * tanha(cn);
                    }
                    stbf2(hp + off, hv[0], hv[1]);
                }
            }
        }
        gbar();
    }
}

// ---------------- finalization ----------------
__global__ void score_k(const float* __restrict__ Wf, const float* __restrict__ bf) {
    int row = blockIdx.x * blockDim.x + threadIdx.x;
    if (row >= EROWS) return;
    const __nv_bfloat16* h = g_hbf[1] + (size_t)row*HD;
    float s = 0.f;
    for (int k = 0; k < HD; k++) s += __bfloat162float(h[k]) * Wf[k];
    g_A[row] = sigf(s + bf[0]);
}
__global__ void assemble_k(float* __restrict__ out) {
    int i = blockIdx.x * blockDim.x + threadIdx.x;
    if (i >= BATCH*NATOM*NATOM) return;
    int b = i / (NATOM*NATOM);
    int nm = i % (NATOM*NATOM);
    int n = nm / NATOM, mm = nm % NATOM;
    float v = 0.f;
    if (n != mm) {
        int e1 = g_einv[n*NATOM + mm];
        int e2 = g_einv[mm*NATOM + n];
        v = 0.5f * (g_A[b*NEDGE + e1] + g_A[b*NEDGE + e2]);
    }
    out[i] = v;
}

// ---------------- launcher ----------------
extern "C" void kernel_launch(void* const* d_in, const int* in_sizes, int n_in,
                              void* d_out, int out_size) {
    const float* X        = (const float*)d_in[0];
    const float* rel_rec  = (const float*)d_in[1];
    const float* rel_send = (const float*)d_in[2];
    const float* Wm  = (const float*)d_in[3];
    const float* bm  = (const float*)d_in[4];
    const float* Wmi = (const float*)d_in[5];
    const float* bmi = (const float*)d_in[6];
    const float* Wmh = (const float*)d_in[7];
    const float* bmh = (const float*)d_in[8];
    const float* We  = (const float*)d_in[9];
    const float* be  = (const float*)d_in[10];
    const float* Wei = (const float*)d_in[11];
    const float* bei = (const float*)d_in[12];
    const float* Weh = (const float*)d_in[13];
    const float* beh = (const float*)d_in[14];
    const float* Wf  = (const float*)d_in[15];
    const float* bf  = (const float*)d_in[16];
    float* out = (float*)d_out;

    static bool attr_done = false;
    if (!attr_done) {
        (void)cudaFuncSetAttribute(gemm_tc_k, cudaFuncAttributeMaxDynamicSharedMemorySize, SMEM_Q);
        (void)cudaFuncSetAttribute(edge_pers_k, cudaFuncAttributeMaxDynamicSharedMemorySize, SMEM_E);
        attr_done = true;
    }

    prep_edges_k<<<2, 256>>>(rel_rec, rel_send);
    prep_rowbase_k<<<(EPAD + 255)/256, 256>>>();
    prep_small_k<<<4, 256>>>(Wm, bm, Wmi, bmi, be, Wei, bei, beh);
    prep_wehI_k<<<(G*HD + 255)/256, 256>>>(Weh);
    prep_wspI_k<<<(2*G*HD + 255)/256, 256>>>(We, Wei);
    zero_state_k<<<(EPAD*HD + 255)/256, 256>>>();

    for (int t = 0; t < TSEQ; t++)
        motion_step_k<4><<<dim3(2, NROWS/4), 128>>>(X, Wmh, bmh, t, t & 1);

    gemm_tc_k<<<dim3(8, MT_G), 256, SMEM_Q>>>(0);
    gemm_tc_k<<<dim3(8, MT_G), 256, SMEM_Q>>>(1);

    edge_pers_k<<<NCTA, 256, SMEM_E>>>();

    score_k<<<(EROWS + 255)/256, 256>>>(Wf, bf);
    assemble_k<<<(BATCH*NATOM*NATOM + 255)/256, 256>>>(out);
}

// round 13
// speedup vs baseline: 1.4831x; 1.2063x over previous
#include <cuda_runtime.h>
#include <cuda_bf16.h>
#include <cstdint>
#include <math.h>

#define BATCH 16
#define NATOM 20
#define NEDGE 380
#define TSEQ  63
#define HD    256
#define G     1024
#define NROWS 320
#define EROWS 6080
#define EPAD  6144
#define MPAD  384
#define HMROWS 20160
#define HMPAD  20224
#define MT_G 158
#define NCTA 128
#define MOT_CTA 24

#define LDK 528
#define ABYTES (128*LDK)            // 67584
#define BOFF   (2*ABYTES)
#define SMEM_E (3*ABYTES)           // 202752
#define SMEM_Q (2*ABYTES)           // 135168

// ---------------- device scratch ----------------
__device__ __nv_bfloat16 g_hmbf[HMPAD*HD];
__device__ __nv_bfloat16 g_Qs[HMPAD*G];        // bf16, permuted cols, +bias
__device__ __nv_bfloat16 g_Qr[HMPAD*G];
__device__ __nv_bfloat16 g_Xg[HMROWS*G];       // motion input proj + all biases, permuted
__device__ __nv_bfloat16 g_hbf[2][EPAD*HD];    // edge h ping-pong
__device__ __nv_bfloat16 g_hnbf[2][MPAD*HD];   // motion h ping-pong
__device__ float g_Wcombp[4*G];                // Wm@Wmi, permuted cols
__device__ float g_bcombp[G];                  // bm@Wmi+bmi+bmh, permuted
__device__ float g_qbias[G];                   // be@Wei+bei+beh, permuted
__device__ __nv_bfloat16 g_WmhI[G*HD];
__device__ __nv_bfloat16 g_WehI[G*HD];
__device__ __nv_bfloat16 g_WspI[2*G*HD];
__device__ int g_send[NEDGE], g_rec[NEDGE], g_einv[NATOM*NATOM];
__device__ int g_sB[EPAD], g_rB[EPAD];
__device__ float g_A[EROWS];
__device__ unsigned g_barCnt, g_mbarCnt;
__device__ volatile unsigned g_barGen, g_mbarGen;

__device__ __forceinline__ float sigf(float x) { return 1.0f / (1.0f + expf(-x)); }
__device__ __forceinline__ float tanha(float x) {
    float y; asm("tanh.approx.f32 %0, %1;" : "=f"(y) : "f"(x)); return y;
}
__device__ __forceinline__ float siga(float x) { return fmaf(0.5f, tanha(0.5f*x), 0.5f); }
__device__ __forceinline__ uint32_t smem_u32(const void* p) {
    uint32_t a;
    asm("{ .reg .u64 t; cvta.to.shared.u64 t, %1; cvt.u32.u64 %0, t; }" : "=r"(a) : "l"(p));
    return a;
}
__device__ __forceinline__ void ldmx4(uint32_t& r0, uint32_t& r1, uint32_t& r2, uint32_t& r3,
                                      uint32_t addr) {
    asm volatile("ldmatrix.sync.aligned.m8n8.x4.shared.b16 {%0,%1,%2,%3}, [%4];"
                 : "=r"(r0), "=r"(r1), "=r"(r2), "=r"(r3) : "r"(addr));
}
__device__ __forceinline__ void mma16816(float* d, uint32_t a0, uint32_t a1, uint32_t a2,
                                         uint32_t a3, uint32_t b0, uint32_t b1) {
    asm volatile(
        "mma.sync.aligned.m16n8k16.row.col.f32.bf16.bf16.f32 "
        "{%0,%1,%2,%3},{%4,%5,%6,%7},{%8,%9},{%0,%1,%2,%3};"
        : "+f"(d[0]), "+f"(d[1]), "+f"(d[2]), "+f"(d[3])
        : "r"(a0), "r"(a1), "r"(a2), "r"(a3), "r"(b0), "r"(b1));
}
__device__ __forceinline__ float2 ldbf2(const __nv_bfloat16* p) {
    return __bfloat1622float2(*(const __nv_bfloat162*)p);
}
__device__ __forceinline__ void stbf2(__nv_bfloat16* p, float a, float b) {
    *(__nv_bfloat162*)p = __floats2bfloat162_rn(a, b);
}
__device__ __forceinline__ void cpasync16(uint32_t dst, const void* src) {
    asm volatile("cp.async.cg.shared.global [%0], [%1], 16;" :: "r"(dst), "l"(src));
}
#define CP_COMMIT() asm volatile("cp.async.commit_group;" ::: "memory")
#define CP_WAIT1()  asm volatile("cp.async.wait_group 1;" ::: "memory")
#define CP_WAIT0()  asm volatile("cp.async.wait_group 0;" ::: "memory")

// bounded-spin grid barrier
__device__ __forceinline__ void gbar(unsigned* cnt, volatile unsigned* gen, unsigned nct) {
    __threadfence();
    __syncthreads();
    if (threadIdx.x == 0) {
        unsigned g = *gen;
        if (atomicAdd(cnt, 1) == nct - 1) {
            *cnt = 0;
            __threadfence();
            *gen = g + 1;
        } else {
            int it = 0;
            while (*gen == g && it < (1 << 21)) { __nanosleep(64); it++; }
            __threadfence();
        }
    }
    __syncthreads();
}

// acc[16][4] = A(128x256,@abuf) @ B(128x256,@BOFF)^T
__device__ __forceinline__ void gemm128(uint32_t sbase, uint32_t abuf, int lane, int wid,
                                        float acc[16][4]) {
#pragma unroll
    for (int i = 0; i < 16; i++)
#pragma unroll
        for (int q = 0; q < 4; q++) acc[i][q] = 0.f;
    uint32_t aadr = sbase + abuf + (wid*16 + (lane & 15))*LDK + (lane >> 4)*16;
    uint32_t badr = sbase + BOFF + (lane & 15)*LDK + (lane >> 4)*16;
#pragma unroll 4
    for (int ks = 0; ks < 16; ks++) {
        uint32_t a0, a1, a2, a3;
        ldmx4(a0, a1, a2, a3, aadr + ks*32);
#pragma unroll
        for (int tp = 0; tp < 8; tp++) {
            uint32_t b0, b1, b2, b3;
            ldmx4(b0, b1, b2, b3, badr + tp*16*LDK + ks*32);
            mma16816(acc[2*tp],     a0, a1, a2, a3, b0, b2);
            mma16816(acc[2*tp + 1], a0, a1, a2, a3, b1, b3);
        }
    }
}
__device__ __forceinline__ void copyA_async(uint32_t sdst, const __nv_bfloat16* src, int tid) {
    const char* s = (const char*)src;
#pragma unroll
    for (int i = 0; i < 16; i++) {
        int idx = tid + i*256;
        cpasync16(sdst + (idx >> 5)*LDK + (idx & 31)*16, s + idx*16);
    }
}
__device__ __forceinline__ void copyB(char* smem, int tid, const __nv_bfloat16* src) {
    const uint4* s = (const uint4*)src;
#pragma unroll
    for (int i = 0; i < 16; i++) {
        int idx = tid + i*256;
        *(uint4*)(smem + BOFF + (idx >> 5)*LDK + (idx & 31)*16) = s[idx];
    }
}

// ---------------- prep kernels ----------------
__global__ void prep_edges_k(const float* __restrict__ rel_rec,
                             const float* __restrict__ rel_send) {
    int e = blockIdx.x * blockDim.x + threadIdx.x;
    if (e >= NEDGE) return;
    int s = 0, r = 0;
    for (int n = 0; n < NATOM; n++) {
        if (rel_send[e*NATOM + n] > 0.5f) s = n;
        if (rel_rec [e*NATOM + n] > 0.5f) r = n;
    }
    g_send[e] = s; g_rec[e] = r;
    g_einv[s*NATOM + r] = e;
}
__global__ void prep_rowbase_k() {
    int grow = blockIdx.x * blockDim.x + threadIdx.x;
    if (grow >= EPAD) return;
    if (grow < EROWS) {
        int b = grow / NEDGE, e = grow - b*NEDGE;
        g_sB[grow] = ((b*NATOM + g_send[e])*TSEQ)*G;
        g_rB[grow] = ((b*NATOM + g_rec [e])*TSEQ)*G;
    } else { g_sB[grow] = 0; g_rB[grow] = 0; }
}
__global__ void prep_small_k(const float* __restrict__ Wm, const float* __restrict__ bm,
                             const float* __restrict__ Wmi, const float* __restrict__ bmi,
                             const float* __restrict__ bmh,
                             const float* __restrict__ be, const float* __restrict__ Wei,
                             const float* __restrict__ bei, const float* __restrict__ beh) {
    int g = blockIdx.x * blockDim.x + threadIdx.x;
    if (g >= G) return;
    int gate = g >> 8, j = g & 255;
    int n = (j >> 5)*128 + gate*32 + (j & 31);
    for (int d = 0; d < 4; d++) {
        float s = 0.f;
        for (int k = 0; k < 128; k++) s += Wm[d*128 + k] * Wmi[k*G + g];
        g_Wcombp[d*G + n] = s;
    }
    float sb = 0.f, sc = 0.f;
    for (int k = 0; k < 128; k++) {
        sb += bm[k] * Wmi[k*G + g];
        sc += be[k] * Wei[k*G + g];
    }
    g_bcombp[n] = sb + bmi[g] + bmh[g];
    g_qbias[n]  = sc + bei[g] + beh[g];
}
__global__ void prep_wI_k(const float* __restrict__ Wmh, const float* __restrict__ Weh) {
    int id = blockIdx.x * blockDim.x + threadIdx.x;
    if (id >= 2*G*HD) return;
    int which = id >> 18;
    int n = (id >> 8) & 1023, k = id & 255;
    int cc = n >> 7, rem = n & 127, gate = rem >> 5, jl = rem & 31;
    int g = gate*256 + cc*32 + jl;
    float v = (which ? Weh : Wmh)[k*G + g];
    (which ? g_WehI : g_WmhI)[n*HD + k] = __float2bfloat16(v);
}
__global__ void prep_wspI_k(const float* __restrict__ We, const float* __restrict__ Wei) {
    int id = blockIdx.x * blockDim.x + threadIdx.x;
    if (id >= 2*G*HD) return;
    int which = id >> 18;
    int k = (id >> 10) & 255;
    int n = id & 1023;
    int cc = n >> 7, rem = n & 127, gate = rem >> 5, jl = rem & 31;
    int gcol = gate*256 + cc*32 + jl;
    const float4* W4 = (const float4*)(We + (which*HD + k)*128);
    float s = 0.f;
#pragma unroll 8
    for (int d4 = 0; d4 < 32; d4++) {
        float4 w = W4[d4];
        s += w.x*Wei[(4*d4+0)*G+gcol] + w.y*Wei[(4*d4+1)*G+gcol]
           + w.z*Wei[(4*d4+2)*G+gcol] + w.w*Wei[(4*d4+3)*G+gcol];
    }
    g_WspI[(which*G + n)*HD + k] = __float2bfloat16(s);
}
__global__ void prep_xg_k(const float* __restrict__ X) {
    int id = blockIdx.x * blockDim.x + threadIdx.x;
    if (id >= HMROWS*G) return;
    int hrow = id >> 10, n = id & 1023;
    int row = hrow / TSEQ, t = hrow - row*TSEQ;
    const float* xp = X + row*256 + t*4;
    float v = g_bcombp[n];
#pragma unroll
    for (int d = 0; d < 4; d++) v += (xp[d+4] - xp[d]) * g_Wcombp[d*G + n];
    g_Xg[id] = __float2bfloat16(v);
}
__global__ void zero_state_k() {
    int i = blockIdx.x * blockDim.x + threadIdx.x;
    if (i < EPAD*HD) {
        g_hbf[0][i] = __float2bfloat16(0.f);
        g_hbf[1][i] = __float2bfloat16(0.f);
    }
    if (i < 2*MPAD*HD) ((__nv_bfloat16*)g_hnbf)[i] = __float2bfloat16(0.f);
    if (i < (HMPAD - HMROWS)*HD) g_hmbf[HMROWS*HD + i] = __float2bfloat16(0.f);
}

// ---------------- persistent motion LSTM (24 CTAs) ----------------
__global__ void __launch_bounds__(256, 1) motion_pers_k() {
    extern __shared__ char smem[];
    int tid = threadIdx.x, c = blockIdx.x;
    int lane = tid & 31, wid = tid >> 5;
    uint32_t sbase = smem_u32(smem);
    int chunk = c & 7, m = c >> 3;          // 8 chunks x 3 m-tiles

    copyB(smem, tid, g_WmhI + (size_t)chunk*128*HD);
    float cR[16];
#pragma unroll
    for (int i = 0; i < 16; i++) cR[i] = 0.f;
    int row0 = m*128 + wid*16 + (lane >> 2);

    for (int t = 0; t < TSEQ; t++) {
        int par = t & 1;
        copyA_async(sbase, g_hnbf[par] + (size_t)m*128*HD, tid);
        CP_COMMIT(); CP_WAIT0();
        __syncthreads();
        float acc[16][4];
        gemm128(sbase, 0, lane, wid, acc);
        __syncthreads();
        __nv_bfloat16* hOut = g_hnbf[par ^ 1];
#pragma unroll
        for (int rr = 0; rr < 2; rr++) {
            int row = row0 + rr*8;
            if (row < NROWS) {
                const __nv_bfloat16* xg = g_Xg + (size_t)(row*TSEQ + t)*G + chunk*128;
                __nv_bfloat16* hp = hOut + (size_t)row*HD + chunk*32;
                __nv_bfloat16* hm = g_hmbf + (size_t)(row*TSEQ + t)*HD + chunk*32;
#pragma unroll
                for (int tq = 0; tq < 4; tq++) {
                    int off = tq*8 + 2*(lane & 3);
                    float2 xi = ldbf2(xg + off),       xf = ldbf2(xg + 32 + off);
                    float2 xgg = ldbf2(xg + 64 + off), xo = ldbf2(xg + 96 + off);
                    float hv[2];
#pragma unroll
                    for (int d = 0; d < 2; d++) {
                        float pi = acc[0*4+tq][rr*2+d] + (d ? xi.y  : xi.x);
                        float pf = acc[1*4+tq][rr*2+d] + (d ? xf.y  : xf.x);
                        float pg = acc[2*4+tq][rr*2+d] + (d ? xgg.y : xgg.x);
                        float po = acc[3*4+tq][rr*2+d] + (d ? xo.y  : xo.x);
                        int ci = rr*8 + tq*2 + d;
                        float iv = siga(pi), fv = siga(pf), gv = tanha(pg), ov = siga(po);
                        float cn = fmaf(fv, cR[ci], iv*gv);
                        cR[ci] = cn;
                        hv[d] = ov * tanha(cn);
                    }
                    stbf2(hp + off, hv[0], hv[1]);
                    stbf2(hm + off, hv[0], hv[1]);
                }
            }
        }
        gbar(&g_mbarCnt, &g_mbarGen, MOT_CTA);
    }
}

// ---------------- TC GEMM: Q{s,r} = hmbf @ WspI (+bias mode 0), bf16 out ----------------
__global__ void __launch_bounds__(256) gemm_tc_k(int mode) {
    extern __shared__ char smem[];
    int tid = threadIdx.x;
    int c = blockIdx.x, m = blockIdx.y;
    uint32_t sbase = smem_u32(smem);
    {
        const uint4* As = (const uint4*)(g_hmbf + (size_t)m*128*HD);
        const uint4* Bs = (const uint4*)(g_WspI + (size_t)(mode*G + c*128)*HD);
#pragma unroll
        for (int i = 0; i < 16; i++) {
            int idx = tid + i*256;
            *(uint4*)(smem + (idx >> 5)*LDK + (idx & 31)*16) = As[idx];
            *(uint4*)(smem + ABYTES + (idx >> 5)*LDK + (idx & 31)*16) = Bs[idx];
        }
        __syncthreads();
    }
    int lane = tid & 31, wid = tid >> 5;
    float acc[16][4];
#pragma unroll
    for (int i = 0; i < 16; i++)
#pragma unroll
        for (int q = 0; q < 4; q++) acc[i][q] = 0.f;
    {
        uint32_t aadr = sbase + (wid*16 + (lane & 15))*LDK + (lane >> 4)*16;
        uint32_t badr = sbase + ABYTES + (lane & 15)*LDK + (lane >> 4)*16;
#pragma unroll 4
        for (int ks = 0; ks < 16; ks++) {
            uint32_t a0, a1, a2, a3;
            ldmx4(a0, a1, a2, a3, aadr + ks*32);
#pragma unroll
            for (int tp = 0; tp < 8; tp++) {
                uint32_t b0, b1, b2, b3;
                ldmx4(b0, b1, b2, b3, badr + tp*16*LDK + ks*32);
                mma16816(acc[2*tp],     a0, a1, a2, a3, b0, b2);
                mma16816(acc[2*tp + 1], a0, a1, a2, a3, b1, b3);
            }
        }
    }
    int row0 = m*128 + wid*16 + (lane >> 2);
    __nv_bfloat16* Qout = mode ? g_Qr : g_Qs;
#pragma unroll
    for (int rr = 0; rr < 2; rr++) {
        int grow = row0 + rr*8;
        if (grow >= HMROWS) continue;
        __nv_bfloat16* op = Qout + (size_t)grow*G + c*128 + 2*(lane & 3);
#pragma unroll
        for (int tt = 0; tt < 16; tt++) {
            float v0 = acc[tt][rr*2], v1 = acc[tt][rr*2+1];
            if (mode == 0) {
                int c0 = c*128 + tt*8 + 2*(lane & 3);
                v0 += g_qbias[c0]; v1 += g_qbias[c0 + 1];
            }
            stbf2(op + tt*8, v0, v1);
        }
    }
}

// ---------------- persistent edge LSTM ----------------
__global__ void __launch_bounds__(256, 1) edge_pers_k() {
    extern __shared__ char smem[];
    int tid = threadIdx.x, c = blockIdx.x;
    int lane = tid & 31, wid = tid >> 5;
    uint32_t sbase = smem_u32(smem);
    int chunk = c & 7, mg = c >> 3;

    copyB(smem, tid, g_WehI + (size_t)chunk*128*HD);
    float cR[3][16];
#pragma unroll
    for (int j = 0; j < 3; j++)
#pragma unroll
        for (int i = 0; i < 16; i++) cR[j][i] = 0.f;

    for (int t = 0; t < TSEQ; t++) {
        int par = t & 1;
        const __nv_bfloat16* hIn = g_hbf[par];
        __nv_bfloat16* hOut = g_hbf[par ^ 1];
        copyA_async(sbase, hIn + (size_t)(mg*3)*128*HD, tid);
        CP_COMMIT();
#pragma unroll 1
        for (int jj = 0; jj < 3; jj++) {
            if (jj < 2) {
                copyA_async(sbase + ((jj+1) & 1)*ABYTES,
                            hIn + (size_t)(mg*3 + jj + 1)*128*HD, tid);
                CP_COMMIT(); CP_WAIT1();
            } else {
                CP_WAIT0();
            }
            __syncthreads();
            float acc[16][4];
            gemm128(sbase, (jj & 1)*ABYTES, lane, wid, acc);
            __syncthreads();
            int row0 = (mg*3 + jj)*128 + wid*16 + (lane >> 2);
#pragma unroll
            for (int rr = 0; rr < 2; rr++) {
                int grow = row0 + rr*8;
                const __nv_bfloat16* qs = g_Qs + g_sB[grow] + t*G + chunk*128;
                const __nv_bfloat16* qr = g_Qr + g_rB[grow] + t*G + chunk*128;
                __nv_bfloat16* hp = hOut + (size_t)grow*HD + chunk*32;
#pragma unroll
                for (int tq = 0; tq < 4; tq++) {
                    int off = tq*8 + 2*(lane & 3);
                    float2 si = ldbf2(qs + off),      ri = ldbf2(qr + off);
                    float2 sf = ldbf2(qs + 32 + off), rf = ldbf2(qr + 32 + off);
                    float2 sg = ldbf2(qs + 64 + off), rg = ldbf2(qr + 64 + off);
                    float2 so = ldbf2(qs + 96 + off), ro = ldbf2(qr + 96 + off);
                    float hv[2];
#pragma unroll
                    for (int d = 0; d < 2; d++) {
                        float pi = acc[0*4+tq][rr*2+d] + (d ? si.y + ri.y : si.x + ri.x);
                        float pf = acc[1*4+tq][rr*2+d] + (d ? sf.y + rf.y : sf.x + rf.x);
                        float pg = acc[2*4+tq][rr*2+d] + (d ? sg.y + rg.y : sg.x + rg.x);
                        float po = acc[3*4+tq][rr*2+d] + (d ? so.y + ro.y : so.x + ro.x);
                        int ci = rr*8 + tq*2 + d;
                        float iv = siga(pi), fv = siga(pf), gv = tanha(pg), ov = siga(po);
                        float cn = fmaf(fv, cR[jj][ci], iv*gv);
                        cR[jj][ci] = cn;
                        hv[d] = ov * tanha(cn);
                    }
                    stbf2(hp + off, hv[0], hv[1]);
                }
            }
        }
        gbar(&g_barCnt, &g_barGen, NCTA);
    }
}

// ---------------- finalization ----------------
__global__ void score_k(const float* __restrict__ Wf, const float* __restrict__ bf) {
    int row = blockIdx.x * blockDim.x + threadIdx.x;
    if (row >= EROWS) return;
    const __nv_bfloat16* h = g_hbf[1] + (size_t)row*HD;
    float s = 0.f;
    for (int k = 0; k < HD; k++) s += __bfloat162float(h[k]) * Wf[k];
    g_A[row] = sigf(s + bf[0]);
}
__global__ void assemble_k(float* __restrict__ out) {
    int i = blockIdx.x * blockDim.x + threadIdx.x;
    if (i >= BATCH*NATOM*NATOM) return;
    int b = i / (NATOM*NATOM);
    int nm = i % (NATOM*NATOM);
    int n = nm / NATOM, mm = nm % NATOM;
    float v = 0.f;
    if (n != mm) {
        int e1 = g_einv[n*NATOM + mm];
        int e2 = g_einv[mm*NATOM + n];
        v = 0.5f * (g_A[b*NEDGE + e1] + g_A[b*NEDGE + e2]);
    }
    out[i] = v;
}

// ---------------- launcher ----------------
extern "C" void kernel_launch(void* const* d_in, const int* in_sizes, int n_in,
                              void* d_out, int out_size) {
    const float* X        = (const float*)d_in[0];
    const float* rel_rec  = (const float*)d_in[1];
    const float* rel_send = (const float*)d_in[2];
    const float* Wm  = (const float*)d_in[3];
    const float* bm  = (const float*)d_in[4];
    const float* Wmi = (const float*)d_in[5];
    const float* bmi = (const float*)d_in[6];
    const float* Wmh = (const float*)d_in[7];
    const float* bmh = (const float*)d_in[8];
    const float* We  = (const float*)d_in[9];
    const float* be  = (const float*)d_in[10];
    const float* Wei = (const float*)d_in[11];
    const float* bei = (const float*)d_in[12];
    const float* Weh = (const float*)d_in[13];
    const float* beh = (const float*)d_in[14];
    const float* Wf  = (const float*)d_in[15];
    const float* bf  = (const float*)d_in[16];
    float* out = (float*)d_out;

    static bool attr_done = false;
    if (!attr_done) {
        (void)cudaFuncSetAttribute(gemm_tc_k, cudaFuncAttributeMaxDynamicSharedMemorySize, SMEM_Q);
        (void)cudaFuncSetAttribute(edge_pers_k, cudaFuncAttributeMaxDynamicSharedMemorySize, SMEM_E);
        (void)cudaFuncSetAttribute(motion_pers_k, cudaFuncAttributeMaxDynamicSharedMemorySize, SMEM_E);
        attr_done = true;
    }

    prep_edges_k<<<2, 256>>>(rel_rec, rel_send);
    prep_rowbase_k<<<(EPAD + 255)/256, 256>>>();
    prep_small_k<<<4, 256>>>(Wm, bm, Wmi, bmi, bmh, be, Wei, bei, beh);
    prep_wI_k<<<(2*G*HD + 255)/256, 256>>>(Wmh, Weh);
    prep_wspI_k<<<(2*G*HD + 255)/256, 256>>>(We, Wei);
    prep_xg_k<<<(HMROWS*G + 255)/256, 256>>>(X);
    zero_state_k<<<(EPAD*HD + 255)/256, 256>>>();

    motion_pers_k<<<MOT_CTA, 256, SMEM_E>>>();

    gemm_tc_k<<<dim3(8, MT_G), 256, SMEM_Q>>>(0);
    gemm_tc_k<<<dim3(8, MT_G), 256, SMEM_Q>>>(1);

    edge_pers_k<<<NCTA, 256, SMEM_E>>>();

    score_k<<<(EROWS + 255)/256, 256>>>(Wf, bf);
    assemble_k<<<(BATCH*NATOM*NATOM + 255)/256, 256>>>(out);
}

// round 14
// speedup vs baseline: 2.3559x; 1.5885x over previous
#include <cuda_runtime.h>
#include <cuda_bf16.h>
#include <cstdint>
#include <math.h>

#define BATCH 16
#define NATOM 20
#define NEDGE 380
#define TSEQ  63
#define HD    256
#define G     1024
#define NROWS 320
#define EROWS 6080
#define EPAD  6144
#define MPAD  384
#define HMROWS 20160
#define HMPAD  20224
#define MT_G 158
#define NCTA 128
#define MOT_CTA 24

#define LDK 528
#define ABYTES (128*LDK)            // 67584
#define BOFF   (2*ABYTES)
#define SMEM_E (3*ABYTES)           // 202752
#define SMEM_Q (2*ABYTES)           // 135168

// ---------------- device scratch ----------------
__device__ __nv_bfloat16 g_hmbf[HMPAD*HD];
__device__ __nv_bfloat16 g_Qs[HMPAD*G];        // bf16, permuted cols, +bias
__device__ __nv_bfloat16 g_Qr[HMPAD*G];
__device__ __nv_bfloat16 g_hbf[2][EPAD*HD];    // edge h ping-pong
__device__ __nv_bfloat16 g_hnbf[2][MPAD*HD];   // motion h ping-pong
__device__ float g_Wcombp[4*G];                // Wm@Wmi, permuted cols
__device__ float g_bcombp[G];                  // bm@Wmi+bmi+bmh, permuted
__device__ float g_qbias[G];                   // be@Wei+bei+beh, permuted
__device__ __nv_bfloat16 g_WmhI[G*HD];
__device__ __nv_bfloat16 g_WehI[G*HD];
__device__ __nv_bfloat16 g_WspI[2*G*HD];
__device__ int g_send[NEDGE], g_rec[NEDGE], g_einv[NATOM*NATOM];
__device__ int g_sB[EPAD], g_rB[EPAD];
__device__ float g_A[EROWS];                   // score accumulators (atomics)
__device__ unsigned g_gCnt[32];                // per-group barrier counters
__device__ volatile unsigned g_gGen[32];

__device__ __forceinline__ float sigf(float x) { return 1.0f / (1.0f + expf(-x)); }
__device__ __forceinline__ float tanha(float x) {
    float y; asm("tanh.approx.f32 %0, %1;" : "=f"(y) : "f"(x)); return y;
}
__device__ __forceinline__ float siga(float x) { return fmaf(0.5f, tanha(0.5f*x), 0.5f); }
__device__ __forceinline__ uint32_t smem_u32(const void* p) {
    uint32_t a;
    asm("{ .reg .u64 t; cvta.to.shared.u64 t, %1; cvt.u32.u64 %0, t; }" : "=r"(a) : "l"(p));
    return a;
}
__device__ __forceinline__ void ldmx4(uint32_t& r0, uint32_t& r1, uint32_t& r2, uint32_t& r3,
                                      uint32_t addr) {
    asm volatile("ldmatrix.sync.aligned.m8n8.x4.shared.b16 {%0,%1,%2,%3}, [%4];"
                 : "=r"(r0), "=r"(r1), "=r"(r2), "=r"(r3) : "r"(addr));
}
__device__ __forceinline__ void mma16816(float* d, uint32_t a0, uint32_t a1, uint32_t a2,
                                         uint32_t a3, uint32_t b0, uint32_t b1) {
    asm volatile(
        "mma.sync.aligned.m16n8k16.row.col.f32.bf16.bf16.f32 "
        "{%0,%1,%2,%3},{%4,%5,%6,%7},{%8,%9},{%0,%1,%2,%3};"
        : "+f"(d[0]), "+f"(d[1]), "+f"(d[2]), "+f"(d[3])
        : "r"(a0), "r"(a1), "r"(a2), "r"(a3), "r"(b0), "r"(b1));
}
__device__ __forceinline__ float2 ldbf2(const __nv_bfloat16* p) {
    return __bfloat1622float2(*(const __nv_bfloat162*)p);
}
__device__ __forceinline__ void stbf2(__nv_bfloat16* p, float a, float b) {
    *(__nv_bfloat162*)p = __floats2bfloat162_rn(a, b);
}
__device__ __forceinline__ void cpasync16(uint32_t dst, const void* src) {
    asm volatile("cp.async.cg.shared.global [%0], [%1], 16;" :: "r"(dst), "l"(src));
}
#define CP_COMMIT() asm volatile("cp.async.commit_group;" ::: "memory")
#define CP_WAIT1()  asm volatile("cp.async.wait_group 1;" ::: "memory")
#define CP_WAIT0()  asm volatile("cp.async.wait_group 0;" ::: "memory")

// bounded-spin GROUP barrier (nct CTAs sharing gid)
__device__ __forceinline__ void gbar_g(int gid, unsigned nct) {
    __threadfence();
    __syncthreads();
    if (threadIdx.x == 0) {
        unsigned g = g_gGen[gid];
        if (atomicAdd(&g_gCnt[gid], 1) == nct - 1) {
            g_gCnt[gid] = 0;
            __threadfence();
            g_gGen[gid] = g + 1;
        } else {
            int it = 0;
            while (g_gGen[gid] == g && it < (1 << 22)) { __nanosleep(32); it++; }
            __threadfence();
        }
    }
    __syncthreads();
}

// acc[16][4] = A(128x256,@abuf) @ B(128x256,@BOFF)^T
__device__ __forceinline__ void gemm128(uint32_t sbase, uint32_t abuf, int lane, int wid,
                                        float acc[16][4]) {
#pragma unroll
    for (int i = 0; i < 16; i++)
#pragma unroll
        for (int q = 0; q < 4; q++) acc[i][q] = 0.f;
    uint32_t aadr = sbase + abuf + (wid*16 + (lane & 15))*LDK + (lane >> 4)*16;
    uint32_t badr = sbase + BOFF + (lane & 15)*LDK + (lane >> 4)*16;
#pragma unroll 4
    for (int ks = 0; ks < 16; ks++) {
        uint32_t a0, a1, a2, a3;
        ldmx4(a0, a1, a2, a3, aadr + ks*32);
#pragma unroll
        for (int tp = 0; tp < 8; tp++) {
            uint32_t b0, b1, b2, b3;
            ldmx4(b0, b1, b2, b3, badr + tp*16*LDK + ks*32);
            mma16816(acc[2*tp],     a0, a1, a2, a3, b0, b2);
            mma16816(acc[2*tp + 1], a0, a1, a2, a3, b1, b3);
        }
    }
}
__device__ __forceinline__ void copyA_async(uint32_t sdst, const __nv_bfloat16* src, int tid) {
    const char* s = (const char*)src;
#pragma unroll
    for (int i = 0; i < 16; i++) {
        int idx = tid + i*256;
        cpasync16(sdst + (idx >> 5)*LDK + (idx & 31)*16, s + idx*16);
    }
}
__device__ __forceinline__ void copyB(char* smem, int tid, const __nv_bfloat16* src) {
    const uint4* s = (const uint4*)src;
#pragma unroll
    for (int i = 0; i < 16; i++) {
        int idx = tid + i*256;
        *(uint4*)(smem + BOFF + (idx >> 5)*LDK + (idx & 31)*16) = s[idx];
    }
}

// ---------------- prep kernels ----------------
__global__ void prep_edges_k(const float* __restrict__ rel_rec,
                             const float* __restrict__ rel_send) {
    int e = blockIdx.x * blockDim.x + threadIdx.x;
    if (e >= NEDGE) return;
    int s = 0, r = 0;
    for (int n = 0; n < NATOM; n++) {
        if (rel_send[e*NATOM + n] > 0.5f) s = n;
        if (rel_rec [e*NATOM + n] > 0.5f) r = n;
    }
    g_send[e] = s; g_rec[e] = r;
    g_einv[s*NATOM + r] = e;
}
__global__ void prep_rowbase_k() {
    int grow = blockIdx.x * blockDim.x + threadIdx.x;
    if (grow >= EPAD) return;
    if (grow < EROWS) {
        int b = grow / NEDGE, e = grow - b*NEDGE;
        g_sB[grow] = ((b*NATOM + g_send[e])*TSEQ)*G;
        g_rB[grow] = ((b*NATOM + g_rec [e])*TSEQ)*G;
    } else { g_sB[grow] = 0; g_rB[grow] = 0; }
}
__global__ void prep_small_k(const float* __restrict__ Wm, const float* __restrict__ bm,
                             const float* __restrict__ Wmi, const float* __restrict__ bmi,
                             const float* __restrict__ bmh,
                             const float* __restrict__ be, const float* __restrict__ Wei,
                             const float* __restrict__ bei, const float* __restrict__ beh) {
    int g = blockIdx.x * blockDim.x + threadIdx.x;
    if (g >= G) return;
    int gate = g >> 8, j = g & 255;
    int n = (j >> 5)*128 + gate*32 + (j & 31);
    for (int d = 0; d < 4; d++) {
        float s = 0.f;
        for (int k = 0; k < 128; k++) s += Wm[d*128 + k] * Wmi[k*G + g];
        g_Wcombp[d*G + n] = s;
    }
    float sb = 0.f, sc = 0.f;
    for (int k = 0; k < 128; k++) {
        sb += bm[k] * Wmi[k*G + g];
        sc += be[k] * Wei[k*G + g];
    }
    g_bcombp[n] = sb + bmi[g] + bmh[g];
    g_qbias[n]  = sc + bei[g] + beh[g];
}
__global__ void prep_wI_k(const float* __restrict__ Wmh, const float* __restrict__ Weh) {
    int id = blockIdx.x * blockDim.x + threadIdx.x;
    if (id >= 2*G*HD) return;
    int which = id >> 18;
    int n = (id >> 8) & 1023, k = id & 255;
    int cc = n >> 7, rem = n & 127, gate = rem >> 5, jl = rem & 31;
    int g = gate*256 + cc*32 + jl;
    float v = (which ? Weh : Wmh)[k*G + g];
    (which ? g_WehI : g_WmhI)[n*HD + k] = __float2bfloat16(v);
}
__global__ void prep_wspI_k(const float* __restrict__ We, const float* __restrict__ Wei) {
    int id = blockIdx.x * blockDim.x + threadIdx.x;
    if (id >= 2*G*HD) return;
    int which = id >> 18;
    int k = (id >> 10) & 255;
    int n = id & 1023;
    int cc = n >> 7, rem = n & 127, gate = rem >> 5, jl = rem & 31;
    int gcol = gate*256 + cc*32 + jl;
    const float4* W4 = (const float4*)(We + (which*HD + k)*128);
    float s = 0.f;
#pragma unroll 8
    for (int d4 = 0; d4 < 32; d4++) {
        float4 w = W4[d4];
        s += w.x*Wei[(4*d4+0)*G+gcol] + w.y*Wei[(4*d4+1)*G+gcol]
           + w.z*Wei[(4*d4+2)*G+gcol] + w.w*Wei[(4*d4+3)*G+gcol];
    }
    g_WspI[(which*G + n)*HD + k] = __float2bfloat16(s);
}
__global__ void zero_state_k() {
    int i = blockIdx.x * blockDim.x + threadIdx.x;
    if (i < EPAD*HD) {
        g_hbf[0][i] = __float2bfloat16(0.f);
        g_hbf[1][i] = __float2bfloat16(0.f);
    }
    if (i < 2*MPAD*HD) ((__nv_bfloat16*)g_hnbf)[i] = __float2bfloat16(0.f);
    if (i < (HMPAD - HMROWS)*HD) g_hmbf[HMROWS*HD + i] = __float2bfloat16(0.f);
    if (i < EROWS) g_A[i] = 0.f;
}

// ---------------- persistent motion LSTM (24 CTAs, group barrier per m-tile) ----------------
__global__ void __launch_bounds__(256, 1) motion_pers_k(const float* __restrict__ X) {
    extern __shared__ char smem[];
    int tid = threadIdx.x, c = blockIdx.x;
    int lane = tid & 31, wid = tid >> 5;
    uint32_t sbase = smem_u32(smem);
    int chunk = c & 7, m = c >> 3;          // 8 chunks x 3 m-tiles; group id = m

    copyB(smem, tid, g_WmhI + (size_t)chunk*128*HD);
    float* WCs = (float*)(smem + ABYTES);            // [4][128]
    float* BSs = (float*)(smem + ABYTES + 2048);     // [128]
    float* Xs  = (float*)(smem + ABYTES + 2560);     // [128][8]
    for (int i = tid; i < 512; i += 256)
        WCs[i] = g_Wcombp[(i >> 7)*G + chunk*128 + (i & 127)];
    for (int i = tid; i < 128; i += 256)
        BSs[i] = g_bcombp[chunk*128 + i];

    float cR[16];
#pragma unroll
    for (int i = 0; i < 16; i++) cR[i] = 0.f;
    int row0 = m*128 + wid*16 + (lane >> 2);

    for (int t = 0; t < TSEQ; t++) {
        int par = t & 1;
        copyA_async(sbase, g_hnbf[par] + (size_t)m*128*HD, tid);
        CP_COMMIT();
        {   // X slice for this m-tile: rows m*128..+127, cols t..t+1 (8 floats)
            int r = tid >> 1, part = tid & 1;
            int gr = m*128 + r;
            float4 v = make_float4(0.f, 0.f, 0.f, 0.f);
            if (gr < NROWS) v = *(const float4*)(X + gr*256 + t*4 + part*4);
            *(float4*)(Xs + r*8 + part*4) = v;
        }
        CP_WAIT0();
        __syncthreads();
        float acc[16][4];
        gemm128(sbase, 0, lane, wid, acc);
        __syncthreads();
        __nv_bfloat16* hOut = g_hnbf[par ^ 1];

        // per-row dX
        float dx[2][4];
        bool rok[2];
#pragma unroll
        for (int rr = 0; rr < 2; rr++) {
            int row = row0 + rr*8;
            rok[rr] = (row < NROWS);
            int lr = (row - m*128) & 127;
            const float* xr = Xs + lr*8;
#pragma unroll
            for (int d = 0; d < 4; d++) dx[rr][d] = xr[d+4] - xr[d];
        }
#pragma unroll
        for (int tq = 0; tq < 4; tq++) {
            float hv[2][2];
#pragma unroll
            for (int d = 0; d < 2; d++) {
                int o = tq*8 + 2*(lane & 3) + d;
                // gate weights (shared across rr)
                float bi = BSs[o],       w0i = WCs[o],       w1i = WCs[128+o],
                      w2i = WCs[256+o],  w3i = WCs[384+o];
                int of = 32 + o;
                float bfv = BSs[of],     w0f = WCs[of],      w1f = WCs[128+of],
                      w2f = WCs[256+of], w3f = WCs[384+of];
                int og = 64 + o;
                float bg = BSs[og],      w0g = WCs[og],      w1g = WCs[128+og],
                      w2g = WCs[256+og], w3g = WCs[384+og];
                int oo = 96 + o;
                float bo = BSs[oo],      w0o = WCs[oo],      w1o = WCs[128+oo],
                      w2o = WCs[256+oo], w3o = WCs[384+oo];
#pragma unroll
                for (int rr = 0; rr < 2; rr++) {
                    float d0 = dx[rr][0], d1 = dx[rr][1], d2 = dx[rr][2], d3 = dx[rr][3];
                    float pi = acc[0*4+tq][rr*2+d] + bi  + d0*w0i + d1*w1i + d2*w2i + d3*w3i;
                    float pf = acc[1*4+tq][rr*2+d] + bfv + d0*w0f + d1*w1f + d2*w2f + d3*w3f;
                    float pg = acc[2*4+tq][rr*2+d] + bg  + d0*w0g + d1*w1g + d2*w2g + d3*w3g;
                    float po = acc[3*4+tq][rr*2+d] + bo  + d0*w0o + d1*w1o + d2*w2o + d3*w3o;
                    int ci = rr*8 + tq*2 + d;
                    float iv = siga(pi), fv = siga(pf), gv = tanha(pg), ov = siga(po);
                    float cn = fmaf(fv, cR[ci], iv*gv);
                    cR[ci] = cn;
                    hv[rr][d] = ov * tanha(cn);
                }
            }
            int off = tq*8 + 2*(lane & 3);
#pragma unroll
            for (int rr = 0; rr < 2; rr++) {
                if (rok[rr]) {
                    int row = row0 + rr*8;
                    stbf2(hOut + (size_t)row*HD + chunk*32 + off, hv[rr][0], hv[rr][1]);
                    stbf2(g_hmbf + (size_t)(row*TSEQ + t)*HD + chunk*32 + off,
                          hv[rr][0], hv[rr][1]);
                }
            }
        }
        if (t < TSEQ - 1) gbar_g(m, 8);
    }
}

// ---------------- TC GEMM: Q{s,r} = hmbf @ WspI (+bias mode 0), bf16 out ----------------
__global__ void __launch_bounds__(256) gemm_tc_k(int mode) {
    extern __shared__ char smem[];
    int tid = threadIdx.x;
    int c = blockIdx.x, m = blockIdx.y;
    uint32_t sbase = smem_u32(smem);
    {
        const uint4* As = (const uint4*)(g_hmbf + (size_t)m*128*HD);
        const uint4* Bs = (const uint4*)(g_WspI + (size_t)(mode*G + c*128)*HD);
#pragma unroll
        for (int i = 0; i < 16; i++) {
            int idx = tid + i*256;
            *(uint4*)(smem + (idx >> 5)*LDK + (idx & 31)*16) = As[idx];
            *(uint4*)(smem + ABYTES + (idx >> 5)*LDK + (idx & 31)*16) = Bs[idx];
        }
        __syncthreads();
    }
    int lane = tid & 31, wid = tid >> 5;
    float acc[16][4];
#pragma unroll
    for (int i = 0; i < 16; i++)
#pragma unroll
        for (int q = 0; q < 4; q++) acc[i][q] = 0.f;
    {
        uint32_t aadr = sbase + (wid*16 + (lane & 15))*LDK + (lane >> 4)*16;
        uint32_t badr = sbase + ABYTES + (lane & 15)*LDK + (lane >> 4)*16;
#pragma unroll 4
        for (int ks = 0; ks < 16; ks++) {
            uint32_t a0, a1, a2, a3;
            ldmx4(a0, a1, a2, a3, aadr + ks*32);
#pragma unroll
            for (int tp = 0; tp < 8; tp++) {
                uint32_t b0, b1, b2, b3;
                ldmx4(b0, b1, b2, b3, badr + tp*16*LDK + ks*32);
                mma16816(acc[2*tp],     a0, a1, a2, a3, b0, b2);
                mma16816(acc[2*tp + 1], a0, a1, a2, a3, b1, b3);
            }
        }
    }
    int row0 = m*128 + wid*16 + (lane >> 2);
    __nv_bfloat16* Qout = mode ? g_Qr : g_Qs;
#pragma unroll
    for (int rr = 0; rr < 2; rr++) {
        int grow = row0 + rr*8;
        if (grow >= HMROWS) continue;
        __nv_bfloat16* op = Qout + (size_t)grow*G + c*128 + 2*(lane & 3);
#pragma unroll
        for (int tt = 0; tt < 16; tt++) {
            float v0 = acc[tt][rr*2], v1 = acc[tt][rr*2+1];
            if (mode == 0) {
                int c0 = c*128 + tt*8 + 2*(lane & 3);
                v0 += g_qbias[c0]; v1 += g_qbias[c0 + 1];
            }
            stbf2(op + tt*8, v0, v1);
        }
    }
}

// ---------------- persistent edge LSTM (group barrier per mg; score fused at t=62) ----------------
__global__ void __launch_bounds__(256, 1) edge_pers_k(const float* __restrict__ Wf) {
    extern __shared__ char smem[];
    int tid = threadIdx.x, c = blockIdx.x;
    int lane = tid & 31, wid = tid >> 5;
    uint32_t sbase = smem_u32(smem);
    int chunk = c & 7, mg = c >> 3;          // group id = 8 + mg (avoid motion gids)

    copyB(smem, tid, g_WehI + (size_t)chunk*128*HD);
    float cR[3][16];
#pragma unroll
    for (int j = 0; j < 3; j++)
#pragma unroll
        for (int i = 0; i < 16; i++) cR[j][i] = 0.f;

    for (int t = 0; t < TSEQ; t++) {
        int par = t & 1;
        const __nv_bfloat16* hIn = g_hbf[par];
        __nv_bfloat16* hOut = g_hbf[par ^ 1];
        bool last = (t == TSEQ - 1);
        copyA_async(sbase, hIn + (size_t)(mg*3)*128*HD, tid);
        CP_COMMIT();
#pragma unroll 1
        for (int jj = 0; jj < 3; jj++) {
            if (jj < 2) {
                copyA_async(sbase + ((jj+1) & 1)*ABYTES,
                            hIn + (size_t)(mg*3 + jj + 1)*128*HD, tid);
                CP_COMMIT(); CP_WAIT1();
            } else {
                CP_WAIT0();
            }
            __syncthreads();
            float acc[16][4];
            gemm128(sbase, (jj & 1)*ABYTES, lane, wid, acc);
            __syncthreads();
            int row0 = (mg*3 + jj)*128 + wid*16 + (lane >> 2);
#pragma unroll
            for (int rr = 0; rr < 2; rr++) {
                int grow = row0 + rr*8;
                const __nv_bfloat16* qs = g_Qs + g_sB[grow] + t*G + chunk*128;
                const __nv_bfloat16* qr = g_Qr + g_rB[grow] + t*G + chunk*128;
                __nv_bfloat16* hp = hOut + (size_t)grow*HD + chunk*32;
                float sacc = 0.f;
#pragma unroll
                for (int tq = 0; tq < 4; tq++) {
                    int off = tq*8 + 2*(lane & 3);
                    float2 si = ldbf2(qs + off),      ri = ldbf2(qr + off);
                    float2 sf = ldbf2(qs + 32 + off), rf = ldbf2(qr + 32 + off);
                    float2 sg = ldbf2(qs + 64 + off), rg = ldbf2(qr + 64 + off);
                    float2 so = ldbf2(qs + 96 + off), ro = ldbf2(qr + 96 + off);
                    float hv[2];
#pragma unroll
                    for (int d = 0; d < 2; d++) {
                        float pi = acc[0*4+tq][rr*2+d] + (d ? si.y + ri.y : si.x + ri.x);
                        float pf = acc[1*4+tq][rr*2+d] + (d ? sf.y + rf.y : sf.x + rf.x);
                        float pg = acc[2*4+tq][rr*2+d] + (d ? sg.y + rg.y : sg.x + rg.x);
                        float po = acc[3*4+tq][rr*2+d] + (d ? so.y + ro.y : so.x + ro.x);
                        int ci = rr*8 + tq*2 + d;
                        float iv = siga(pi), fv = siga(pf), gv = tanha(pg), ov = siga(po);
                        float cn = fmaf(fv, cR[jj][ci], iv*gv);
                        cR[jj][ci] = cn;
                        hv[d] = ov * tanha(cn);
                    }
                    if (!last) {
                        stbf2(hp + off, hv[0], hv[1]);
                    } else {
                        sacc += hv[0]*Wf[chunk*32 + off] + hv[1]*Wf[chunk*32 + off + 1];
                    }
                }
                if (last && grow < EROWS) atomicAdd(&g_A[grow], sacc);
            }
        }
        if (!last) gbar_g(8 + mg, 8);
    }
}

// ---------------- finalization ----------------
__global__ void assemble_k(const float* __restrict__ bf, float* __restrict__ out) {
    int i = blockIdx.x * blockDim.x + threadIdx.x;
    if (i >= BATCH*NATOM*NATOM) return;
    float b0 = bf[0];
    int b = i / (NATOM*NATOM);
    int nm = i % (NATOM*NATOM);
    int n = nm / NATOM, mm = nm % NATOM;
    float v = 0.f;
    if (n != mm) {
        int e1 = g_einv[n*NATOM + mm];
        int e2 = g_einv[mm*NATOM + n];
        v = 0.5f * (sigf(g_A[b*NEDGE + e1] + b0) + sigf(g_A[b*NEDGE + e2] + b0));
    }
    out[i] = v;
}

// ---------------- launcher ----------------
extern "C" void kernel_launch(void* const* d_in, const int* in_sizes, int n_in,
                              void* d_out, int out_size) {
    const float* X        = (const float*)d_in[0];
    const float* rel_rec  = (const float*)d_in[1];
    const float* rel_send = (const float*)d_in[2];
    const float* Wm  = (const float*)d_in[3];
    const float* bm  = (const float*)d_in[4];
    const float* Wmi = (const float*)d_in[5];
    const float* bmi = (const float*)d_in[6];
    const float* Wmh = (const float*)d_in[7];
    const float* bmh = (const float*)d_in[8];
    const float* We  = (const float*)d_in[9];
    const float* be  = (const float*)d_in[10];
    const float* Wei = (const float*)d_in[11];
    const float* bei = (const float*)d_in[12];
    const float* Weh = (const float*)d_in[13];
    const float* beh = (const float*)d_in[14];
    const float* Wf  = (const float*)d_in[15];
    const float* bf  = (const float*)d_in[16];
    float* out = (float*)d_out;

    static bool attr_done = false;
    if (!attr_done) {
        (void)cudaFuncSetAttribute(gemm_tc_k, cudaFuncAttributeMaxDynamicSharedMemorySize, SMEM_Q);
        (void)cudaFuncSetAttribute(edge_pers_k, cudaFuncAttributeMaxDynamicSharedMemorySize, SMEM_E);
        (void)cudaFuncSetAttribute(motion_pers_k, cudaFuncAttributeMaxDynamicSharedMemorySize, SMEM_E);
        attr_done = true;
    }

    prep_edges_k<<<2, 256>>>(rel_rec, rel_send);
    prep_rowbase_k<<<(EPAD + 255)/256, 256>>>();
    prep_small_k<<<4, 256>>>(Wm, bm, Wmi, bmi, bmh, be, Wei, bei, beh);
    prep_wI_k<<<(2*G*HD + 255)/256, 256>>>(Wmh, Weh);
    prep_wspI_k<<<(2*G*HD + 255)/256, 256>>>(We, Wei);
    zero_state_k<<<(EPAD*HD + 255)/256, 256>>>();

    motion_pers_k<<<MOT_CTA, 256, SMEM_E>>>(X);

    gemm_tc_k<<<dim3(8, MT_G), 256, SMEM_Q>>>(0);
    gemm_tc_k<<<dim3(8, MT_G), 256, SMEM_Q>>>(1);

    edge_pers_k<<<NCTA, 256, SMEM_E>>>(Wf);

    assemble_k<<<(BATCH*NATOM*NATOM + 255)/256, 256>>>(bf, out);
}

// round 16
// speedup vs baseline: 2.8238x; 1.1986x over previous
#include <cuda_runtime.h>
#include <cuda_bf16.h>
#include <cstdint>
#include <math.h>

#define BATCH 16
#define NATOM 20
#define NEDGE 380
#define TSEQ  63
#define HD    256
#define G     1024
#define NROWS 320
#define EROWS 6080
#define EPAD  6144
#define HMROWS 20160
#define HMPAD  20224
#define MT_G 158
#define NCTA 128
#define MOT_CTA 40

#define LDK 528
#define ABYTES (128*LDK)            // 67584
#define BOFF   (2*ABYTES)
#define SMEM_E (3*ABYTES)           // 202752
#define SMEM_Q (2*ABYTES)           // 135168

// ---------------- device scratch ----------------
__device__ __nv_bfloat16 g_hmbf[HMPAD*HD];
__device__ __nv_bfloat16 g_Qs[HMPAD*G];        // bf16, vector layout, +bias
__device__ __nv_bfloat16 g_Qr[HMPAD*G];
__device__ __nv_bfloat16 g_hbf[2][EPAD*HD];    // edge h ping-pong
__device__ __nv_bfloat16 g_hnbf[2][NROWS*HD];  // motion h ping-pong
__device__ float g_WcombM[4*G];                // Wm@Wmi, MOTION permutation
__device__ float g_bcombM[G];                  // bm@Wmi+bmi+bmh, MOTION perm
__device__ float g_qbias[G];                   // be@Wei+bei+beh, Q perm
__device__ __nv_bfloat16 g_WmhM[G*HD];         // Wmh^T, motion perm, k-contig
__device__ __nv_bfloat16 g_WehI[G*HD];         // Weh^T, edge perm
__device__ __nv_bfloat16 g_WspI[2*G*HD];
__device__ int g_send[NEDGE], g_rec[NEDGE], g_einv[NATOM*NATOM];
__device__ int g_sB[EPAD], g_rB[EPAD];
__device__ float g_A[EROWS];
__device__ unsigned g_gCnt[32];
__device__ volatile unsigned g_gGen[32];

__device__ __forceinline__ float sigf(float x) { return 1.0f / (1.0f + expf(-x)); }
__device__ __forceinline__ float tanha(float x) {
    float y; asm("tanh.approx.f32 %0, %1;" : "=f"(y) : "f"(x)); return y;
}
__device__ __forceinline__ float siga(float x) { return fmaf(0.5f, tanha(0.5f*x), 0.5f); }
__device__ __forceinline__ uint32_t smem_u32(const void* p) {
    uint32_t a;
    asm("{ .reg .u64 t; cvta.to.shared.u64 t, %1; cvt.u32.u64 %0, t; }" : "=r"(a) : "l"(p));
    return a;
}
__device__ __forceinline__ void ldmx4(uint32_t& r0, uint32_t& r1, uint32_t& r2, uint32_t& r3,
                                      uint32_t addr) {
    asm volatile("ldmatrix.sync.aligned.m8n8.x4.shared.b16 {%0,%1,%2,%3}, [%4];"
                 : "=r"(r0), "=r"(r1), "=r"(r2), "=r"(r3) : "r"(addr));
}
__device__ __forceinline__ void mma16816(float* d, uint32_t a0, uint32_t a1, uint32_t a2,
                                         uint32_t a3, uint32_t b0, uint32_t b1) {
    asm volatile(
        "mma.sync.aligned.m16n8k16.row.col.f32.bf16.bf16.f32 "
        "{%0,%1,%2,%3},{%4,%5,%6,%7},{%8,%9},{%0,%1,%2,%3};"
        : "+f"(d[0]), "+f"(d[1]), "+f"(d[2]), "+f"(d[3])
        : "r"(a0), "r"(a1), "r"(a2), "r"(a3), "r"(b0), "r"(b1));
}
__device__ __forceinline__ void stbf2(__nv_bfloat16* p, float a, float b) {
    *(__nv_bfloat162*)p = __floats2bfloat162_rn(a, b);
}
// load 8 bf16 from a and b, return elementwise float sum as 4 float2
__device__ __forceinline__ void ldq8(float2 o[4], const __nv_bfloat16* a,
                                     const __nv_bfloat16* b) {
    uint4 ua = *(const uint4*)a, ub = *(const uint4*)b;
    const __nv_bfloat162* pa = (const __nv_bfloat162*)&ua;
    const __nv_bfloat162* pb = (const __nv_bfloat162*)&ub;
#pragma unroll
    for (int i = 0; i < 4; i++) {
        float2 x = __bfloat1622float2(pa[i]);
        float2 y = __bfloat1622float2(pb[i]);
        o[i] = make_float2(x.x + y.x, x.y + y.y);
    }
}
__device__ __forceinline__ void cpasync16(uint32_t dst, const void* src) {
    asm volatile("cp.async.cg.shared.global [%0], [%1], 16;" :: "r"(dst), "l"(src));
}
#define CP_COMMIT() asm volatile("cp.async.commit_group;" ::: "memory")
#define CP_WAIT1()  asm volatile("cp.async.wait_group 1;" ::: "memory")
#define CP_WAIT0()  asm volatile("cp.async.wait_group 0;" ::: "memory")

__device__ __forceinline__ void gbar_g(int gid, unsigned nct) {
    __threadfence();
    __syncthreads();
    if (threadIdx.x == 0) {
        unsigned g = g_gGen[gid];
        if (atomicAdd(&g_gCnt[gid], 1) == nct - 1) {
            g_gCnt[gid] = 0;
            __threadfence();
            g_gGen[gid] = g + 1;
        } else {
            int it = 0;
            while (g_gGen[gid] == g && it < (1 << 22)) { __nanosleep(32); it++; }
            __threadfence();
        }
    }
    __syncthreads();
}

// acc[16][4] = A(128x256,@abuf) @ B(128x256,@BOFF)^T
__device__ __forceinline__ void gemm128(uint32_t sbase, uint32_t abuf, int lane, int wid,
                                        float acc[16][4]) {
#pragma unroll
    for (int i = 0; i < 16; i++)
#pragma unroll
        for (int q = 0; q < 4; q++) acc[i][q] = 0.f;
    uint32_t aadr = sbase + abuf + (wid*16 + (lane & 15))*LDK + (lane >> 4)*16;
    uint32_t badr = sbase + BOFF + (lane & 15)*LDK + (lane >> 4)*16;
#pragma unroll 4
    for (int ks = 0; ks < 16; ks++) {
        uint32_t a0, a1, a2, a3;
        ldmx4(a0, a1, a2, a3, aadr + ks*32);
#pragma unroll
        for (int tp = 0; tp < 8; tp++) {
            uint32_t b0, b1, b2, b3;
            ldmx4(b0, b1, b2, b3, badr + tp*16*LDK + ks*32);
            mma16816(acc[2*tp],     a0, a1, a2, a3, b0, b2);
            mma16816(acc[2*tp + 1], a0, a1, a2, a3, b1, b3);
        }
    }
}
// acc[8][4] = A(64x256)@ (B 64-col half of chunk)^T : warp wq owns 16 rows, wh col half
__device__ __forceinline__ void gemm64(uint32_t sbase, int lane, int wq, int wh,
                                       float acc[8][4]) {
#pragma unroll
    for (int i = 0; i < 8; i++)
#pragma unroll
        for (int q = 0; q < 4; q++) acc[i][q] = 0.f;
    uint32_t aadr = sbase + (wq*16 + (lane & 15))*LDK + (lane >> 4)*16;
    uint32_t badr = sbase + BOFF + (wh*64 + (lane & 15))*LDK + (lane >> 4)*16;
#pragma unroll 4
    for (int ks = 0; ks < 16; ks++) {
        uint32_t a0, a1, a2, a3;
        ldmx4(a0, a1, a2, a3, aadr + ks*32);
#pragma unroll
        for (int tp = 0; tp < 4; tp++) {
            uint32_t b0, b1, b2, b3;
            ldmx4(b0, b1, b2, b3, badr + tp*16*LDK + ks*32);
            mma16816(acc[2*tp],     a0, a1, a2, a3, b0, b2);
            mma16816(acc[2*tp + 1], a0, a1, a2, a3, b1, b3);
        }
    }
}
__device__ __forceinline__ void copyA_async(uint32_t sdst, const __nv_bfloat16* src, int tid) {
    const char* s = (const char*)src;
#pragma unroll
    for (int i = 0; i < 16; i++) {
        int idx = tid + i*256;
        cpasync16(sdst + (idx >> 5)*LDK + (idx & 31)*16, s + idx*16);
    }
}
// 64 rows x 256 cols bf16 = 32768 B = 2048 x 16B chunks -> 8 iterations of 256 threads
__device__ __forceinline__ void copyA64_async(uint32_t sdst, const __nv_bfloat16* src, int tid) {
    const char* s = (const char*)src;
#pragma unroll
    for (int i = 0; i < 8; i++) {
        int idx = tid + i*256;
        cpasync16(sdst + (idx >> 5)*LDK + (idx & 31)*16, s + idx*16);
    }
}
__device__ __forceinline__ void copyB(char* smem, int tid, const __nv_bfloat16* src) {
    const uint4* s = (const uint4*)src;
#pragma unroll
    for (int i = 0; i < 16; i++) {
        int idx = tid + i*256;
        *(uint4*)(smem + BOFF + (idx >> 5)*LDK + (idx & 31)*16) = s[idx];
    }
}

// ---------------- prep kernels ----------------
__global__ void prep_edges_k(const float* __restrict__ rel_rec,
                             const float* __restrict__ rel_send) {
    int e = blockIdx.x * blockDim.x + threadIdx.x;
    if (e >= NEDGE) return;
    int s = 0, r = 0;
    for (int n = 0; n < NATOM; n++) {
        if (rel_send[e*NATOM + n] > 0.5f) s = n;
        if (rel_rec [e*NATOM + n] > 0.5f) r = n;
    }
    g_send[e] = s; g_rec[e] = r;
    g_einv[s*NATOM + r] = e;
}
__global__ void prep_rowbase_k() {
    int grow = blockIdx.x * blockDim.x + threadIdx.x;
    if (grow >= EPAD) return;
    if (grow < EROWS) {
        int b = grow / NEDGE, e = grow - b*NEDGE;
        g_sB[grow] = ((b*NATOM + g_send[e])*TSEQ)*G;
        g_rB[grow] = ((b*NATOM + g_rec [e])*TSEQ)*G;
    } else { g_sB[grow] = 0; g_rB[grow] = 0; }
}
// Edge Q perm: q(g) ; Motion perm: nM(g)
__global__ void prep_small_k(const float* __restrict__ Wm, const float* __restrict__ bm,
                             const float* __restrict__ Wmi, const float* __restrict__ bmi,
                             const float* __restrict__ bmh,
                             const float* __restrict__ be, const float* __restrict__ Wei,
                             const float* __restrict__ bei, const float* __restrict__ beh) {
    int g = blockIdx.x * blockDim.x + threadIdx.x;
    if (g >= G) return;
    int gate = g >> 8, j = g & 255;
    int jl = j & 31;
    // edge Q layout: chunk*128 + gate*32 + lane3*8 + tq*2 + d
    int q = (j >> 5)*128 + gate*32 + ((jl & 7) >> 1)*8 + (jl >> 3)*2 + (jl & 1);
    // motion layout: cc*128 + wh*64 + (hh*4+gate)*8 + r
    int nM = (j >> 5)*128 + ((j >> 4) & 1)*64 + ((((j >> 3) & 1)*4 + gate))*8 + (j & 7);
    float sb = 0.f, sc = 0.f;
    for (int k = 0; k < 128; k++) {
        sb += bm[k] * Wmi[k*G + g];
        sc += be[k] * Wei[k*G + g];
    }
    for (int d = 0; d < 4; d++) {
        float s = 0.f;
        for (int k = 0; k < 128; k++) s += Wm[d*128 + k] * Wmi[k*G + g];
        g_WcombM[d*G + nM] = s;
    }
    g_bcombM[nM] = sb + bmi[g] + bmh[g];
    g_qbias[q]   = sc + bei[g] + beh[g];
}
__global__ void prep_wI_k(const float* __restrict__ Wmh, const float* __restrict__ Weh) {
    int id = blockIdx.x * blockDim.x + threadIdx.x;
    if (id >= 2*G*HD) return;
    int which = id >> 18;
    int n = (id >> 8) & 1023, k = id & 255;
    if (which == 0) {
        // motion perm: n -> (gate, j)
        int cc = n >> 7, loc = n & 127, wh = loc >> 6, l2 = loc & 63;
        int tile = l2 >> 3, r = l2 & 7;
        int g = (tile & 3)*256 + cc*32 + wh*16 + (tile >> 2)*8 + r;
        g_WmhM[n*HD + k] = __float2bfloat16(Wmh[k*G + g]);
    } else {
        // edge perm: n = cc*128 + gate*32 + jl
        int cc = n >> 7, rem = n & 127, gate = rem >> 5, jl = rem & 31;
        int g = gate*256 + cc*32 + jl;
        g_WehI[n*HD + k] = __float2bfloat16(Weh[k*G + g]);
    }
}
__global__ void prep_wspI_k(const float* __restrict__ We, const float* __restrict__ Wei) {
    int id = blockIdx.x * blockDim.x + threadIdx.x;
    if (id >= 2*G*HD) return;
    int which = id >> 18;
    int k = (id >> 10) & 255;
    int n = id & 1023;
    int cc = n >> 7, rem = n & 127, gate = rem >> 5, jl = rem & 31;
    int gcol = gate*256 + cc*32 + jl;
    const float4* W4 = (const float4*)(We + (which*HD + k)*128);
    float s = 0.f;
#pragma unroll 8
    for (int d4 = 0; d4 < 32; d4++) {
        float4 w = W4[d4];
        s += w.x*Wei[(4*d4+0)*G+gcol] + w.y*Wei[(4*d4+1)*G+gcol]
           + w.z*Wei[(4*d4+2)*G+gcol] + w.w*Wei[(4*d4+3)*G+gcol];
    }
    g_WspI[(which*G + n)*HD + k] = __float2bfloat16(s);
}
__global__ void zero_state_k() {
    int i = blockIdx.x * blockDim.x + threadIdx.x;
    if (i < EPAD*HD) {
        g_hbf[0][i] = __float2bfloat16(0.f);
        g_hbf[1][i] = __float2bfloat16(0.f);
    }
    if (i < 2*NROWS*HD) ((__nv_bfloat16*)g_hnbf)[i] = __float2bfloat16(0.f);
    if (i < (HMPAD - HMROWS)*HD) g_hmbf[HMROWS*HD + i] = __float2bfloat16(0.f);
    if (i < EROWS) g_A[i] = 0.f;
}

// ---------------- persistent motion LSTM (40 CTAs, 64-row tiles) ----------------
__global__ void __launch_bounds__(256, 1) motion_pers_k(const float* __restrict__ X) {
    extern __shared__ char smem[];
    int tid = threadIdx.x, c = blockIdx.x;
    int lane = tid & 31, wid = tid >> 5;
    int lane3 = lane & 3;
    uint32_t sbase = smem_u32(smem);
    int chunk = c & 7, mgrp = c >> 3;   // 8 chunks x 5 row-groups; gid = mgrp
    int wq = wid & 3, wh = wid >> 2;

    copyB(smem, tid, g_WmhM + (size_t)chunk*128*HD);
    float* WCs = (float*)(smem + ABYTES);          // [4][128]
    float* BSs = (float*)(smem + ABYTES + 2048);   // [128]
    float* Xs  = (float*)(smem + ABYTES + 2560);   // [64][8]
    for (int i = tid; i < 512; i += 256)
        WCs[i] = g_WcombM[(i >> 7)*G + chunk*128 + (i & 127)];
    for (int i = tid; i < 128; i += 256)
        BSs[i] = g_bcombM[chunk*128 + i];

    float cR[8];
#pragma unroll
    for (int i = 0; i < 8; i++) cR[i] = 0.f;
    int row0 = mgrp*64 + wq*16 + (lane >> 2);

    for (int t = 0; t < TSEQ; t++) {
        int par = t & 1;
        copyA64_async(sbase, g_hnbf[par] + (size_t)mgrp*64*HD, tid);
        CP_COMMIT();
        if (tid < 128) {
            int r = tid >> 1, part = tid & 1;
            int gr = mgrp*64 + r;
            *(float4*)(Xs + r*8 + part*4) = *(const float4*)(X + gr*256 + t*4 + part*4);
        }
        CP_WAIT0();
        __syncthreads();
        float acc[8][4];
        gemm64(sbase, lane, wq, wh, acc);
        __syncthreads();
        __nv_bfloat16* hOut = g_hnbf[par ^ 1];
#pragma unroll
        for (int rr = 0; rr < 2; rr++) {
            int row = row0 + rr*8;
            int lr = row - mgrp*64;
            const float* xr = Xs + lr*8;
            float d0 = xr[4]-xr[0], d1 = xr[5]-xr[1], d2 = xr[6]-xr[2], d3 = xr[7]-xr[3];
            __nv_bfloat16* hp = hOut + (size_t)row*HD + chunk*32 + wh*16;
            __nv_bfloat16* hm = g_hmbf + (size_t)(row*TSEQ + t)*HD + chunk*32 + wh*16;
#pragma unroll
            for (int hh = 0; hh < 2; hh++) {
                float hv[2];
#pragma unroll
                for (int d = 0; d < 2; d++) {
                    float pre[4];
#pragma unroll
                    for (int gq = 0; gq < 4; gq++) {
                        int loc = wh*64 + (hh*4 + gq)*8 + 2*lane3 + d;
                        pre[gq] = acc[hh*4 + gq][rr*2 + d] + BSs[loc]
                                + d0*WCs[loc] + d1*WCs[128+loc]
                                + d2*WCs[256+loc] + d3*WCs[384+loc];
                    }
                    int ci = rr*4 + hh*2 + d;
                    float iv = siga(pre[0]), fv = siga(pre[1]);
                    float gv = tanha(pre[2]), ov = siga(pre[3]);
                    float cn = fmaf(fv, cR[ci], iv*gv);
                    cR[ci] = cn;
                    hv[d] = ov * tanha(cn);
                }
                stbf2(hp + hh*8 + 2*lane3, hv[0], hv[1]);
                stbf2(hm + hh*8 + 2*lane3, hv[0], hv[1]);
            }
        }
        if (t < TSEQ - 1) gbar_g(mgrp, 8);
    }
}

// ---------------- TC GEMM: Q{s,r} = hmbf @ WspI (+bias mode 0), vector layout out ----------------
__global__ void __launch_bounds__(256) gemm_tc_k() {
    extern __shared__ char smem[];
    int tid = threadIdx.x;
    int c = blockIdx.x & 7, mode = blockIdx.x >> 3, m = blockIdx.y;
    uint32_t sbase = smem_u32(smem);
    {
        const uint4* As = (const uint4*)(g_hmbf + (size_t)m*128*HD);
        const uint4* Bs = (const uint4*)(g_WspI + (size_t)(mode*G + c*128)*HD);
#pragma unroll
        for (int i = 0; i < 16; i++) {
            int idx = tid + i*256;
            *(uint4*)(smem + (idx >> 5)*LDK + (idx & 31)*16) = As[idx];
            *(uint4*)(smem + ABYTES + (idx >> 5)*LDK + (idx & 31)*16) = Bs[idx];
        }
        __syncthreads();
    }
    int lane = tid & 31, wid = tid >> 5;
    float acc[16][4];
#pragma unroll
    for (int i = 0; i < 16; i++)
#pragma unroll
        for (int q = 0; q < 4; q++) acc[i][q] = 0.f;
    {
        uint32_t aadr = sbase + (wid*16 + (lane & 15))*LDK + (lane >> 4)*16;
        uint32_t badr = sbase + ABYTES + (lane & 15)*LDK + (lane >> 4)*16;
#pragma unroll 4
        for (int ks = 0; ks < 16; ks++) {
            uint32_t a0, a1, a2, a3;
            ldmx4(a0, a1, a2, a3, aadr + ks*32);
#pragma unroll
            for (int tp = 0; tp < 8; tp++) {
                uint32_t b0, b1, b2, b3;
                ldmx4(b0, b1, b2, b3, badr + tp*16*LDK + ks*32);
                mma16816(acc[2*tp],     a0, a1, a2, a3, b0, b2);
                mma16816(acc[2*tp + 1], a0, a1, a2, a3, b1, b3);
            }
        }
    }
    int row0 = m*128 + wid*16 + (lane >> 2);
    __nv_bfloat16* Qout = mode ? g_Qr : g_Qs;
#pragma unroll
    for (int rr = 0; rr < 2; rr++) {
        int grow = row0 + rr*8;
        if (grow >= HMROWS) continue;
        __nv_bfloat16* op = Qout + (size_t)grow*G + c*128;
#pragma unroll
        for (int tt = 0; tt < 16; tt++) {
            int p = (tt >> 2)*32 + (lane & 3)*8 + (tt & 3)*2;
            float v0 = acc[tt][rr*2], v1 = acc[tt][rr*2+1];
            if (mode == 0) {
                v0 += g_qbias[c*128 + p]; v1 += g_qbias[c*128 + p + 1];
            }
            stbf2(op + p, v0, v1);
        }
    }
}

// ---------------- persistent edge LSTM ----------------
__global__ void __launch_bounds__(256, 1) edge_pers_k(const float* __restrict__ Wf) {
    extern __shared__ char smem[];
    int tid = threadIdx.x, c = blockIdx.x;
    int lane = tid & 31, wid = tid >> 5;
    int lane3 = lane & 3;
    uint32_t sbase = smem_u32(smem);
    int chunk = c & 7, mg = c >> 3;          // gid = 8 + mg

    copyB(smem, tid, g_WehI + (size_t)chunk*128*HD);
    float cR[3][16];
#pragma unroll
    for (int j = 0; j < 3; j++)
#pragma unroll
        for (int i = 0; i < 16; i++) cR[j][i] = 0.f;

    for (int t = 0; t < TSEQ; t++) {
        int par = t & 1;
        const __nv_bfloat16* hIn = g_hbf[par];
        __nv_bfloat16* hOut = g_hbf[par ^ 1];
        bool last = (t == TSEQ - 1);
        copyA_async(sbase, hIn + (size_t)(mg*3)*128*HD, tid);
        CP_COMMIT();
#pragma unroll 1
        for (int jj = 0; jj < 3; jj++) {
            if (jj < 2) {
                copyA_async(sbase + ((jj+1) & 1)*ABYTES,
                            hIn + (size_t)(mg*3 + jj + 1)*128*HD, tid);
                CP_COMMIT(); CP_WAIT1();
            } else {
                CP_WAIT0();
            }
            __syncthreads();
            float acc[16][4];
            gemm128(sbase, (jj & 1)*ABYTES, lane, wid, acc);
            __syncthreads();
            int row0 = (mg*3 + jj)*128 + wid*16 + (lane >> 2);
#pragma unroll
            for (int rr = 0; rr < 2; rr++) {
                int grow = row0 + rr*8;
                const __nv_bfloat16* qs = g_Qs + g_sB[grow] + t*G + chunk*128 + lane3*8;
                const __nv_bfloat16* qr = g_Qr + g_rB[grow] + t*G + chunk*128 + lane3*8;
                __nv_bfloat16* hp = hOut + (size_t)grow*HD + chunk*32;
                float2 qi[4], qf[4], qg[4], qo[4];
                ldq8(qi, qs,      qr);
                ldq8(qf, qs + 32, qr + 32);
                ldq8(qg, qs + 64, qr + 64);
                ldq8(qo, qs + 96, qr + 96);
                float sacc = 0.f;
#pragma unroll
                for (int tq = 0; tq < 4; tq++) {
                    float hv[2];
#pragma unroll
                    for (int d = 0; d < 2; d++) {
                        float pi = acc[0*4+tq][rr*2+d] + (d ? qi[tq].y : qi[tq].x);
                        float pf = acc[1*4+tq][rr*2+d] + (d ? qf[tq].y : qf[tq].x);
                        float pg = acc[2*4+tq][rr*2+d] + (d ? qg[tq].y : qg[tq].x);
                        float po = acc[3*4+tq][rr*2+d] + (d ? qo[tq].y : qo[tq].x);
                        int ci = rr*8 + tq*2 + d;
                        float iv = siga(pi), fv = siga(pf), gv = tanha(pg), ov = siga(po);
                        float cn = fmaf(fv, cR[jj][ci], iv*gv);
                        cR[jj][ci] = cn;
                        hv[d] = ov * tanha(cn);
                    }
                    int off = tq*8 + 2*lane3;
                    if (!last) {
                        stbf2(hp + off, hv[0], hv[1]);
                    } else {
                        sacc += hv[0]*Wf[chunk*32 + off] + hv[1]*Wf[chunk*32 + off + 1];
                    }
                }
                if (last && grow < EROWS) atomicAdd(&g_A[grow], sacc);
            }
        }
        if (!last) gbar_g(8 + mg, 8);
    }
}

// ---------------- finalization ----------------
__global__ void assemble_k(const float* __restrict__ bf, float* __restrict__ out) {
    int i = blockIdx.x * blockDim.x + threadIdx.x;
    if (i >= BATCH*NATOM*NATOM) return;
    float b0 = bf[0];
    int b = i / (NATOM*NATOM);
    int nm = i % (NATOM*NATOM);
    int n = nm / NATOM, mm = nm % NATOM;
    float v = 0.f;
    if (n != mm) {
        int e1 = g_einv[n*NATOM + mm];
        int e2 = g_einv[mm*NATOM + n];
        v = 0.5f * (sigf(g_A[b*NEDGE + e1] + b0) + sigf(g_A[b*NEDGE + e2] + b0));
    }
    out[i] = v;
}

// ---------------- launcher ----------------
extern "C" void kernel_launch(void* const* d_in, const int* in_sizes, int n_in,
                              void* d_out, int out_size) {
    const float* X        = (const float*)d_in[0];
    const float* rel_rec  = (const float*)d_in[1];
    const float* rel_send = (const float*)d_in[2];
    const float* Wm  = (const float*)d_in[3];
    const float* bm  = (const float*)d_in[4];
    const float* Wmi = (const float*)d_in[5];
    const float* bmi = (const float*)d_in[6];
    const float* Wmh = (const float*)d_in[7];
    const float* bmh = (const float*)d_in[8];
    const float* We  = (const float*)d_in[9];
    const float* be  = (const float*)d_in[10];
    const float* Wei = (const float*)d_in[11];
    const float* bei = (const float*)d_in[12];
    const float* Weh = (const float*)d_in[13];
    const float* beh = (const float*)d_in[14];
    const float* Wf  = (const float*)d_in[15];
    const float* bf  = (const float*)d_in[16];
    float* out = (float*)d_out;

    static bool attr_done = false;
    if (!attr_done) {
        (void)cudaFuncSetAttribute(gemm_tc_k, cudaFuncAttributeMaxDynamicSharedMemorySize, SMEM_Q);
        (void)cudaFuncSetAttribute(edge_pers_k, cudaFuncAttributeMaxDynamicSharedMemorySize, SMEM_E);
        (void)cudaFuncSetAttribute(motion_pers_k, cudaFuncAttributeMaxDynamicSharedMemorySize, SMEM_E);
        attr_done = true;
    }

    prep_edges_k<<<2, 256>>>(rel_rec, rel_send);
    prep_rowbase_k<<<(EPAD + 255)/256, 256>>>();
    prep_small_k<<<4, 256>>>(Wm, bm, Wmi, bmi, bmh, be, Wei, bei, beh);
    prep_wI_k<<<(2*G*HD + 255)/256, 256>>>(Wmh, Weh);
    prep_wspI_k<<<(2*G*HD + 255)/256, 256>>>(We, Wei);
    zero_state_k<<<(EPAD*HD + 255)/256, 256>>>();

    motion_pers_k<<<MOT_CTA, 256, SMEM_E>>>(X);

    gemm_tc_k<<<dim3(16, MT_G), 256, SMEM_Q>>>();

    edge_pers_k<<<NCTA, 256, SMEM_E>>>(Wf);

    assemble_k<<<(BATCH*NATOM*NATOM + 255)/256, 256>>>(bf, out);
}